// round 13
// baseline (speedup 1.0000x reference)
#include <cuda_runtime.h>
#include <cuda_fp16.h>
#include <cstdint>
#include <cstddef>

#define BATCH   2
#define SEQLEN  4096
#define DMODEL  512
#define DINNER  1024
#define NH      16
#define HD      64
#define DSTATE  64
#define CONVDIM 1152
#define DPROJ   2192
#define NPOS    (BATCH * SEQLEN)   // 8192
#define NC      64
#define CS      64
#define EPSV    1e-5f
#define NPAD1   2304

// ---------------- scratch (static device globals) ---------------------------
__device__ float  g_zx [(size_t)NPOS * DPROJ];
__device__ __half g_xbc[(size_t)NPOS * CONVDIM];   // fp16: conv output
__device__ float  g_dt [NPOS * NH];
__device__ float  g_cl [BATCH * NH * SEQLEN];
__device__ float  g_S  [(size_t)BATCH * NH * NC * HD * DSTATE];
__device__ __half g_Sh [(size_t)BATCH * NH * NC * HD * DSTATE];  // fp16 prefix states
__device__ float  g_y  [(size_t)NPOS * DINNER];

__device__ __half g_xh [(size_t)NPOS * DMODEL];
__device__ __half g_w1h[(size_t)NPAD1 * DMODEL];
__device__ __half g_yh [(size_t)NPOS * DINNER];
__device__ __half g_w2h[(size_t)DMODEL * DINNER];

// ---------------- PTX helpers ------------------------------------------------
__device__ __forceinline__ uint32_t smem_u32(const void* p) {
  uint32_t a;
  asm("{ .reg .u64 t; cvta.to.shared.u64 t, %1; cvt.u32.u64 %0, t; }" : "=r"(a) : "l"(p));
  return a;
}
__device__ __forceinline__ void ldm4(uint32_t* r, uint32_t addr) {
  asm volatile("ldmatrix.sync.aligned.m8n8.x4.shared.b16 {%0,%1,%2,%3}, [%4];"
               : "=r"(r[0]), "=r"(r[1]), "=r"(r[2]), "=r"(r[3]) : "r"(addr));
}
__device__ __forceinline__ void ldm4t(uint32_t* r, uint32_t addr) {
  asm volatile("ldmatrix.sync.aligned.m8n8.x4.trans.shared.b16 {%0,%1,%2,%3}, [%4];"
               : "=r"(r[0]), "=r"(r[1]), "=r"(r[2]), "=r"(r[3]) : "r"(addr));
}
__device__ __forceinline__ void mma16816(float* c, const uint32_t* a, const uint32_t* b) {
  asm volatile(
      "mma.sync.aligned.m16n8k16.row.col.f32.f16.f16.f32 "
      "{%0,%1,%2,%3}, {%4,%5,%6,%7}, {%8,%9}, {%0,%1,%2,%3};"
      : "+f"(c[0]), "+f"(c[1]), "+f"(c[2]), "+f"(c[3])
      : "r"(a[0]), "r"(a[1]), "r"(a[2]), "r"(a[3]), "r"(b[0]), "r"(b[1]));
}
#define CPASYNC(dst, src) \
  asm volatile("cp.async.cg.shared.global [%0], [%1], 16;" :: "r"(dst), "l"(src))
#define CPCOMMIT() asm volatile("cp.async.commit_group;" ::: "memory")
#define CPWAIT(n)  asm volatile("cp.async.wait_group %0;" :: "n"(n) : "memory")
#define SWZ(off)   ((off) ^ (((off) >> 3) & 0x70))

// ---------------- HMMA GEMM (fp16): C = A @ B^T ------------------------------
#define SM_BUF   32768
#define SM_TOTAL (3 * SM_BUF)

__global__ __launch_bounds__(128, 2) void gemm_tc(
    const __half* __restrict__ A, const __half* __restrict__ B,
    float* __restrict__ C, int K, int N, int ldc) {
  extern __shared__ char smem[];
  const uint32_t sb = smem_u32(smem);
  const int tid = threadIdx.x, wid = tid >> 5, lane = tid & 31;
  const int bm = blockIdx.y * 128, bn = blockIdx.x * 128;
  const int wrow = wid & 1, wcol = wid >> 1;

  float acc[4][8][4];
  #pragma unroll
  for (int i = 0; i < 4; i++)
    #pragma unroll
    for (int j = 0; j < 8; j++)
      #pragma unroll
      for (int v = 0; v < 4; v++) acc[i][j][v] = 0.f;

  const int nK = K >> 6;

  #pragma unroll
  for (int pre = 0; pre < 2; pre++) {
    if (pre < nK) {
      const int k0 = pre << 6;
      const uint32_t bbuf = sb + pre * SM_BUF;
      #pragma unroll
      for (int it = 0; it < 16; it++) {
        const int u = it * 128 + tid;
        const int tile = u >> 10, idx = u & 1023;
        const int row = idx >> 3, c16 = idx & 7;
        const uint32_t dst = bbuf + tile * 16384 + SWZ((uint32_t)(row * 128 + c16 * 16));
        const __half* src = (tile == 0) ? A + (size_t)(bm + row) * K + k0 + c16 * 8
                                        : B + (size_t)(bn + row) * K + k0 + c16 * 8;
        CPASYNC(dst, src);
      }
    }
    CPCOMMIT();
  }

  int buf = 0;
  for (int i = 0; i < nK; i++) {
    if (i + 2 < nK) {
      const int k0 = (i + 2) << 6;
      const uint32_t bbuf = sb + ((buf + 2 >= 3) ? buf - 1 : buf + 2) * SM_BUF;
      #pragma unroll
      for (int it = 0; it < 16; it++) {
        const int u = it * 128 + tid;
        const int tile = u >> 10, idx = u & 1023;
        const int row = idx >> 3, c16 = idx & 7;
        const uint32_t dst = bbuf + tile * 16384 + SWZ((uint32_t)(row * 128 + c16 * 16));
        const __half* src = (tile == 0) ? A + (size_t)(bm + row) * K + k0 + c16 * 8
                                        : B + (size_t)(bn + row) * K + k0 + c16 * 8;
        CPASYNC(dst, src);
      }
    }
    CPCOMMIT();
    CPWAIT(2);
    __syncthreads();

    const uint32_t tb = sb + buf * SM_BUF;
    const int arow = wrow * 64 + (lane & 15);
    const int brow = wcol * 64 + (lane & 7) + ((lane >> 4) & 1) * 8;
    const int akb  = (lane >> 4) * 16;
    const int bkb  = ((lane >> 3) & 1) * 16;

    #pragma unroll
    for (int ks = 0; ks < 4; ks++) {
      uint32_t ah[4][4];
      #pragma unroll
      for (int mt = 0; mt < 4; mt++) {
        const uint32_t off = SWZ((uint32_t)((arow + mt * 16) * 128 + ks * 32 + akb));
        ldm4(ah[mt], tb + off);
      }
      #pragma unroll
      for (int p = 0; p < 4; p++) {
        uint32_t bf[4];
        const uint32_t off = SWZ((uint32_t)((brow + p * 16) * 128 + ks * 32 + bkb));
        ldm4(bf, tb + 16384 + off);
        #pragma unroll
        for (int mt = 0; mt < 4; mt++) {
          mma16816(acc[mt][2 * p],     ah[mt], &bf[0]);
          mma16816(acc[mt][2 * p + 1], ah[mt], &bf[2]);
        }
      }
    }
    __syncthreads();
    buf = (buf + 1 >= 3) ? 0 : buf + 1;
  }

  const int r0 = bm + wrow * 64 + (lane >> 2);
  const int c0 = bn + wcol * 64 + (lane & 3) * 2;
  #pragma unroll
  for (int mt = 0; mt < 4; mt++)
    #pragma unroll
    for (int nt = 0; nt < 8; nt++) {
      const int col = c0 + nt * 8;
      if (col < N) {
        const int row = r0 + mt * 16;
        *(float2*)&C[(size_t)row * ldc + col] =
            make_float2(acc[mt][nt][0], acc[mt][nt][1]);
        *(float2*)&C[(size_t)(row + 8) * ldc + col] =
            make_float2(acc[mt][nt][2], acc[mt][nt][3]);
      }
    }
}

// ---------------- fp32 -> fp16 cast ------------------------------------------
__global__ void tofp16_kernel(const float* __restrict__ src,
                              __half* __restrict__ dst, int n) {
  int i = blockIdx.x * 256 + threadIdx.x;
  if (i < n) dst[i] = __float2half(src[i]);
}

// ---------------- W transpose -> fp16 ----------------------------------------
__global__ void wtrans_kernel(const float* __restrict__ W,
                              __half* __restrict__ th, int K, int N) {
  __shared__ float t[32][33];
  const int n0 = blockIdx.x * 32, k0 = blockIdx.y * 32;
  const int tx = threadIdx.x, ty = threadIdx.y;
  #pragma unroll
  for (int r = 0; r < 4; r++) {
    int k = k0 + ty + r * 8, n = n0 + tx;
    t[ty + r * 8][tx] = (n < N) ? W[(size_t)k * N + n] : 0.f;
  }
  __syncthreads();
  #pragma unroll
  for (int r = 0; r < 4; r++) {
    int n = n0 + ty + r * 8, k = k0 + tx;
    th[(size_t)n * K + k] = __float2half(t[tx][ty + r * 8]);
  }
}

// ---------------- depthwise conv + bias + SiLU -> fp16 -----------------------
__global__ __launch_bounds__(128) void conv_kernel(const float* __restrict__ cw,
                                                   const float* __restrict__ cb) {
  const int ch  = blockIdx.x * 128 + threadIdx.x;
  const int grp = blockIdx.y;
  const size_t pos0 = (size_t)grp * 8;
  const int l0 = (int)(pos0 & (SEQLEN - 1));
  const float* src = g_zx + pos0 * DPROJ + DINNER + ch;
  const float w0 = cw[ch * 4 + 0], w1 = cw[ch * 4 + 1];
  const float w2 = cw[ch * 4 + 2], w3 = cw[ch * 4 + 3];
  const float bias = cb[ch];
  float v[11];
  #pragma unroll
  for (int j = 0; j < 3; j++)
    v[j] = (l0 >= 3 - j) ? src[(ptrdiff_t)(j - 3) * DPROJ] : 0.f;
  #pragma unroll
  for (int j = 0; j < 8; j++)
    v[3 + j] = src[(ptrdiff_t)j * DPROJ];
  __half* dst = g_xbc + pos0 * CONVDIM + ch;
  #pragma unroll
  for (int j = 0; j < 8; j++) {
    float a = bias + w0 * v[j] + w1 * v[j + 1] + w2 * v[j + 2] + w3 * v[j + 3];
    dst[(size_t)j * CONVDIM] = __float2half(a / (1.f + __expf(-a)));
  }
}

// ---------------- fused dt softplus + per-chunk cumsum (warp/chunk) ---------
__global__ void dtscan_kernel(const float* __restrict__ dtb,
                              const float* __restrict__ alog) {
  const int gw = (blockIdx.x * 256 + threadIdx.x) >> 5;
  const int lane = threadIdx.x & 31;
  const int c = gw & (NC - 1);
  const int bh = gw >> 6;
  const int b = bh >> 4, h = bh & (NH - 1);
  const int t0 = c * CS;
  const int pos0 = b * SEQLEN + t0 + lane;
  const float bsh = dtb[h];
  const float A = -expf(alog[h]);
  float v0 = g_zx[(size_t)pos0 * DPROJ + DINNER + CONVDIM + h] + bsh;
  float v1 = g_zx[(size_t)(pos0 + 32) * DPROJ + DINNER + CONVDIM + h] + bsh;
  float sp0 = (v0 > 20.f) ? v0 : log1pf(expf(v0));
  float sp1 = (v1 > 20.f) ? v1 : log1pf(expf(v1));
  g_dt[pos0 * NH + h] = sp0;
  g_dt[(pos0 + 32) * NH + h] = sp1;
  float x0 = A * sp0, x1 = A * sp1;
  #pragma unroll
  for (int o = 1; o < 32; o <<= 1) {
    float t = __shfl_up_sync(0xFFFFFFFFu, x0, o);
    if (lane >= o) x0 += t;
  }
  float tot0 = __shfl_sync(0xFFFFFFFFu, x0, 31);
  #pragma unroll
  for (int o = 1; o < 32; o <<= 1) {
    float t = __shfl_up_sync(0xFFFFFFFFu, x1, o);
    if (lane >= o) x1 += t;
  }
  x1 += tot0;
  g_cl[bh * SEQLEN + t0 + lane] = x0;
  g_cl[bh * SEQLEN + t0 + 32 + lane] = x1;
}

// ---------------- intra-chunk SSD kernel (HMMA, head-batched) ----------------
// One CTA per (b, chunk, head-group-of-4). B/C loaded once; M0 = C@B^T
// computed once and held in register fragments; 4 heads processed in a loop.
#define CLDH 72
#define CLDB 144
#define CH_SMEM (4 * 9216 + 128 * 4)

__global__ __launch_bounds__(256) void chunk_kernel(const float* __restrict__ Dv) {
  extern __shared__ __align__(16) __half sh[];
  __half* sB  = sh;            // [64][72] B[s][n]
  __half* sCX = sh + 4608;     // [64][72] C[t][n], then X[s][p] per head
  __half* sM  = sh + 9216;     // [64][72] M[t][s] per head
  __half* sXW = sh + 13824;    // [64][72] XW[s][p] per head
  float* scl = (float*)(sh + 18432);
  float* sdt = scl + 64;

  const int bid = blockIdx.x;
  const int hg = bid & 3;                 // head group (4 heads each)
  const int c  = (bid >> 2) & (NC - 1);
  const int b  = bid >> 8;
  const int tid = threadIdx.x;
  const int t0 = c * CS;
  const int wid = tid >> 5, lane = tid & 31;

  // ---- load B, C once ----
  {
    const int row = tid >> 2, cs = (tid & 3) * 16;
    const __half* base = g_xbc + (size_t)(b * SEQLEN + t0 + row) * CONVDIM;
    #pragma unroll
    for (int q = 0; q < 2; q++) {
      const int col = cs + q * 8;
      *(uint4*)(sB  + row * CLDH + col) = *(const uint4*)(base + DINNER + col);
      *(uint4*)(sCX + row * CLDH + col) = *(const uint4*)(base + DINNER + DSTATE + col);
    }
  }
  __syncthreads();

  const uint32_t uB = smem_u32(sB), uCX = smem_u32(sCX);
  const uint32_t uM = smem_u32(sM), uXW = smem_u32(sXW);
  const int mt0 = (wid & 3) * 16;
  const int nt0 = (wid >> 2) * 32;
  const int aoff = (lane & 15) * CLDB + (lane >> 4) * 16;
  const int boff = ((lane & 7) + ((lane >> 4) & 1) * 8) * CLDB + ((lane >> 3) & 1) * 16;
  const int bofft_row = (lane & 7) + ((lane >> 3) & 1) * 8;
  const int bofft_b   = ((lane >> 4) & 1) * 16;
  const int aofft_row = (lane & 7) + ((lane >> 4) & 1) * 8;
  const int aofft_b   = ((lane >> 3) & 1) * 16;
  const int rb = mt0 + (lane >> 2);
  const int cb = nt0 + (lane & 3) * 2;

  // ---- GEMM0 (head-independent): M0 = C @ B^T, kept in registers ----
  float m0[4][4];
  #pragma unroll
  for (int nt = 0; nt < 4; nt++)
    #pragma unroll
    for (int v = 0; v < 4; v++) m0[nt][v] = 0.f;
  #pragma unroll
  for (int ks = 0; ks < 4; ks++) {
    uint32_t af[4];
    ldm4(af, uCX + (uint32_t)(mt0 * CLDB + aoff + ks * 32));
    #pragma unroll
    for (int p = 0; p < 2; p++) {
      uint32_t bf[4];
      ldm4(bf, uB + (uint32_t)((nt0 + p * 16) * CLDB + boff + ks * 32));
      mma16816(m0[2 * p],     af, &bf[0]);
      mma16816(m0[2 * p + 1], af, &bf[2]);
    }
  }

  // ---- per-head loop ----
  for (int hh = 0; hh < 4; hh++) {
    const int h = hg * 4 + hh;
    __syncthreads();   // prior reads of sCX/sM/sXW complete
    {
      const int row = tid >> 2, cs = (tid & 3) * 16;
      const __half* base = g_xbc + (size_t)(b * SEQLEN + t0 + row) * CONVDIM + h * HD;
      #pragma unroll
      for (int q = 0; q < 2; q++)
        *(uint4*)(sCX + row * CLDH + cs + q * 8) = *(const uint4*)(base + cs + q * 8);
      if (tid < 64) {
        scl[tid] = g_cl[(b * NH + h) * SEQLEN + t0 + tid];
        sdt[tid] = g_dt[(b * SEQLEN + t0 + tid) * NH + h];
      }
    }
    __syncthreads();   // X, scl, sdt visible

    // build masked decay matrix M from register M0
    #pragma unroll
    for (int nt = 0; nt < 4; nt++)
      #pragma unroll
      for (int cc = 0; cc < 4; cc++) {
        const int t = rb + ((cc >> 1) << 3);
        const int s = cb + nt * 8 + (cc & 1);
        float v = m0[nt][cc];
        v = (s <= t) ? v * __expf(scl[t] - scl[s]) * sdt[s] : 0.f;
        sM[t * CLDH + s] = __float2half(v);
      }
    // XW[s][p] = w[s] * X[s][p]  (own-row data, no cross-thread dep)
    {
      const float Ltot = scl[63];
      const int row = tid >> 2, cs = (tid & 3) * 16;
      const float w = __expf(Ltot - scl[row]) * sdt[row];
      #pragma unroll
      for (int j = 0; j < 16; j++) {
        const int o = row * CLDH + cs + j;
        sXW[o] = __float2half(__half2float(sCX[o]) * w);
      }
    }
    __syncthreads();   // sM, sXW visible

    float acc[4][4];
    // ---- GEMM2: Y = M @ X  (A non-trans from M; B trans from X[s][p]) ----
    #pragma unroll
    for (int nt = 0; nt < 4; nt++)
      #pragma unroll
      for (int v = 0; v < 4; v++) acc[nt][v] = 0.f;
    #pragma unroll
    for (int ks = 0; ks < 4; ks++) {
      uint32_t af[4];
      ldm4(af, uM + (uint32_t)(mt0 * CLDB + aoff + ks * 32));
      #pragma unroll
      for (int p = 0; p < 2; p++) {
        uint32_t bf[4];
        ldm4t(bf, uCX + (uint32_t)((ks * 16 + bofft_row) * CLDB
                                   + (nt0 + p * 16) * 2 + bofft_b));
        mma16816(acc[2 * p],     af, &bf[0]);
        mma16816(acc[2 * p + 1], af, &bf[2]);
      }
    }
    {
      const float Dh = Dv[h];
      #pragma unroll
      for (int nt = 0; nt < 4; nt++) {
        const int p = cb + nt * 8;
        const int t1 = rb, t2 = rb + 8;
        float2 o01 = make_float2(
            acc[nt][0] + Dh * __half2float(sCX[t1 * CLDH + p]),
            acc[nt][1] + Dh * __half2float(sCX[t1 * CLDH + p + 1]));
        float2 o23 = make_float2(
            acc[nt][2] + Dh * __half2float(sCX[t2 * CLDH + p]),
            acc[nt][3] + Dh * __half2float(sCX[t2 * CLDH + p + 1]));
        *(float2*)&g_y[(size_t)(b * SEQLEN + t0 + t1) * DINNER + h * HD + p] = o01;
        *(float2*)&g_y[(size_t)(b * SEQLEN + t0 + t2) * DINNER + h * HD + p] = o23;
      }
    }

    // ---- GEMM3: S = XW^T @ B  (A trans from XW[s][p]; B trans from B[s][n]) --
    #pragma unroll
    for (int nt = 0; nt < 4; nt++)
      #pragma unroll
      for (int v = 0; v < 4; v++) acc[nt][v] = 0.f;
    #pragma unroll
    for (int ks = 0; ks < 4; ks++) {
      uint32_t af[4];
      ldm4t(af, uXW + (uint32_t)((ks * 16 + aofft_row) * CLDB + mt0 * 2 + aofft_b));
      #pragma unroll
      for (int p = 0; p < 2; p++) {
        uint32_t bf[4];
        ldm4t(bf, uB + (uint32_t)((ks * 16 + bofft_row) * CLDB
                                  + (nt0 + p * 16) * 2 + bofft_b));
        mma16816(acc[2 * p],     af, &bf[0]);
        mma16816(acc[2 * p + 1], af, &bf[2]);
      }
    }
    const size_t sbase = (size_t)((b * NH + h) * NC + c) * 4096;
    #pragma unroll
    for (int nt = 0; nt < 4; nt++) {
      const int n = cb + nt * 8;
      *(float2*)&g_S[sbase + rb * 64 + n] = make_float2(acc[nt][0], acc[nt][1]);
      *(float2*)&g_S[sbase + (rb + 8) * 64 + n] = make_float2(acc[nt][2], acc[nt][3]);
    }
  }
}

// ---------------- inter-chunk state scan (fp32 in, fp16 prefix out) ---------
__global__ __launch_bounds__(128) void scan_kernel() {
  const int bh = blockIdx.x;
  const int slice = blockIdx.y;
  const int tid = threadIdx.x;
  const int off = slice * 512 + tid * 4;
  float run[4] = {0.f, 0.f, 0.f, 0.f};
  for (int c = 0; c < NC; c++) {
    float a = __expf(g_cl[bh * SEQLEN + c * CS + CS - 1]);
    const float* p = g_S + (size_t)(bh * NC + c) * 4096 + off;
    float4 v = *(const float4*)p;
    __half2* d = (__half2*)(g_Sh + (size_t)(bh * NC + c) * 4096 + off);
    d[0] = __floats2half2_rn(run[0], run[1]);
    d[1] = __floats2half2_rn(run[2], run[3]);
    run[0] = a * run[0] + v.x;
    run[1] = a * run[1] + v.y;
    run[2] = a * run[2] + v.z;
    run[3] = a * run[3] + v.w;
  }
}

// ---------------- inter-chunk contribution (HMMA fp16) ----------------------
__global__ __launch_bounds__(256) void inter_kernel() {
  __shared__ __align__(16) __half sC[4608];   // [64][72] C[t][n]
  __shared__ __align__(16) __half sS[4608];   // [64][72] Sprev[p][n]
  __shared__ float scl[64];
  const int bid = blockIdx.x;
  const int c = bid & (NC - 1);
  const int bh = bid >> 6;
  const int h = bh & (NH - 1);
  const int b = bh >> 4;
  const int tid = threadIdx.x;
  const int t0 = c * CS;
  const int wid = tid >> 5, lane = tid & 31;

  {
    const int row = tid >> 2, cs = (tid & 3) * 16;
    const __half* cbase = g_xbc + (size_t)(b * SEQLEN + t0 + row) * CONVDIM
                          + DINNER + DSTATE;
    #pragma unroll
    for (int q = 0; q < 2; q++) {
      *(uint4*)(sC + row * CLDH + cs + q * 8) = *(const uint4*)(cbase + cs + q * 8);
      *(uint4*)(sS + row * CLDH + cs + q * 8) =
          *(const uint4*)(g_Sh + (size_t)bid * 4096 + row * 64 + cs + q * 8);
    }
    if (tid < 64) scl[tid] = g_cl[bh * SEQLEN + t0 + tid];
  }
  __syncthreads();

  const uint32_t uC = smem_u32(sC), uS = smem_u32(sS);
  const int mt0 = (wid & 3) * 16;
  const int nt0 = (wid >> 2) * 32;
  const int aoff = (lane & 15) * CLDB + (lane >> 4) * 16;
  const int boff = ((lane & 7) + ((lane >> 4) & 1) * 8) * CLDB + ((lane >> 3) & 1) * 16;
  const int rb = mt0 + (lane >> 2);
  const int cb = nt0 + (lane & 3) * 2;

  float acc[4][4];
  #pragma unroll
  for (int nt = 0; nt < 4; nt++)
    #pragma unroll
    for (int v = 0; v < 4; v++) acc[nt][v] = 0.f;
  #pragma unroll
  for (int ks = 0; ks < 4; ks++) {
    uint32_t af[4];
    ldm4(af, uC + (uint32_t)(mt0 * CLDB + aoff + ks * 32));
    #pragma unroll
    for (int p = 0; p < 2; p++) {
      uint32_t bf[4];
      ldm4(bf, uS + (uint32_t)((nt0 + p * 16) * CLDB + boff + ks * 32));
      mma16816(acc[2 * p],     af, &bf[0]);
      mma16816(acc[2 * p + 1], af, &bf[2]);
    }
  }
  const float e1 = __expf(scl[rb]);
  const float e2 = __expf(scl[rb + 8]);
  #pragma unroll
  for (int nt = 0; nt < 4; nt++) {
    const int p = cb + nt * 8;
    size_t o1 = (size_t)(b * SEQLEN + t0 + rb) * DINNER + h * HD + p;
    size_t o2 = (size_t)(b * SEQLEN + t0 + rb + 8) * DINNER + h * HD + p;
    float2 c1 = *(float2*)&g_y[o1];
    float2 c2 = *(float2*)&g_y[o2];
    c1.x += e1 * acc[nt][0]; c1.y += e1 * acc[nt][1];
    c2.x += e2 * acc[nt][2]; c2.y += e2 * acc[nt][3];
    *(float2*)&g_y[o1] = c1;
    *(float2*)&g_y[o2] = c2;
  }
}

// ---------------- gate + RMSNorm, emits fp16 ---------------------------------
__global__ __launch_bounds__(256) void norm_kernel(const float* __restrict__ nw) {
  const int pos = blockIdx.x, tid = threadIdx.x;
  float4 yv = *(const float4*)(g_y  + (size_t)pos * DINNER + tid * 4);
  float4 zv = *(const float4*)(g_zx + (size_t)pos * DPROJ  + tid * 4);
  float4 g;
  g.x = yv.x * (zv.x / (1.f + __expf(-zv.x)));
  g.y = yv.y * (zv.y / (1.f + __expf(-zv.y)));
  g.z = yv.z * (zv.z / (1.f + __expf(-zv.z)));
  g.w = yv.w * (zv.w / (1.f + __expf(-zv.w)));
  float ssq = g.x * g.x + g.y * g.y + g.z * g.z + g.w * g.w;
  #pragma unroll
  for (int o = 16; o; o >>= 1) ssq += __shfl_xor_sync(0xFFFFFFFFu, ssq, o);
  __shared__ float red[8];
  if ((tid & 31) == 0) red[tid >> 5] = ssq;
  __syncthreads();
  float tot = red[0] + red[1] + red[2] + red[3] + red[4] + red[5] + red[6] + red[7];
  float scale = rsqrtf(tot * (1.f / DINNER) + EPSV);
  float4 w = *(const float4*)(nw + tid * 4);
  __half2* dst = (__half2*)(g_yh + (size_t)pos * DINNER + tid * 4);
  dst[0] = __floats2half2_rn(g.x * scale * w.x, g.y * scale * w.y);
  dst[1] = __floats2half2_rn(g.z * scale * w.z, g.w * scale * w.w);
}

// ---------------- launch ------------------------------------------------------
extern "C" void kernel_launch(void* const* d_in, const int* in_sizes, int n_in,
                              void* d_out, int out_size) {
  const float* x       = (const float*)d_in[0];
  const float* W_in    = (const float*)d_in[1];
  const float* conv_w  = (const float*)d_in[2];
  const float* conv_b  = (const float*)d_in[3];
  const float* dt_bias = (const float*)d_in[4];
  const float* A_log   = (const float*)d_in[5];
  const float* Dv      = (const float*)d_in[6];
  const float* nw      = (const float*)d_in[7];
  const float* W_out   = (const float*)d_in[8];
  float* out = (float*)d_out;

  void* p;
  cudaGetSymbolAddress(&p, g_zx);  float* zx = (float*)p;
  cudaGetSymbolAddress(&p, g_xh);  __half* xh  = (__half*)p;
  cudaGetSymbolAddress(&p, g_w1h); __half* w1h = (__half*)p;
  cudaGetSymbolAddress(&p, g_yh);  __half* yh  = (__half*)p;
  cudaGetSymbolAddress(&p, g_w2h); __half* w2h = (__half*)p;

  cudaFuncSetAttribute(chunk_kernel, cudaFuncAttributeMaxDynamicSharedMemorySize, CH_SMEM);
  cudaFuncSetAttribute(gemm_tc, cudaFuncAttributeMaxDynamicSharedMemorySize, SM_TOTAL);

  dim3 blk(256);
  tofp16_kernel<<<(NPOS * DMODEL) / 256, blk>>>(x, xh, NPOS * DMODEL);
  wtrans_kernel<<<dim3(NPAD1 / 32, DMODEL / 32), dim3(32, 8)>>>(W_in, w1h, DMODEL, DPROJ);
  wtrans_kernel<<<dim3(DMODEL / 32, DINNER / 32), dim3(32, 8)>>>(W_out, w2h, DINNER, DMODEL);
  // 1) in-projection
  gemm_tc<<<dim3(NPAD1 / 128, NPOS / 128), dim3(128), SM_TOTAL>>>(xh, w1h, zx,
                                                                  DMODEL, DPROJ, DPROJ);
  // 2) conv + silu -> fp16
  conv_kernel<<<dim3(CONVDIM / 128, NPOS / 8), dim3(128)>>>(conv_w, conv_b);
  // 3) fused dt + cumlog
  dtscan_kernel<<<(BATCH * NH * NC * 32) / 256, blk>>>(dt_bias, A_log);
  // 4) intra-chunk SSD (HMMA, head-batched: one CTA per (b,c,4-head group))
  chunk_kernel<<<BATCH * NC * 4, blk, CH_SMEM>>>(Dv);
  // 5) inter-chunk state scan
  scan_kernel<<<dim3(BATCH * NH, 8), dim3(128)>>>();
  // 6) inter-chunk correction (HMMA)
  inter_kernel<<<BATCH * NH * NC, blk>>>();
  // 7) gate + RMSNorm
  norm_kernel<<<NPOS, blk>>>(nw);
  // 8) out-projection
  gemm_tc<<<dim3(DMODEL / 128, NPOS / 128), dim3(128), SM_TOTAL>>>(yh, w2h, out,
                                                                   DINNER, DMODEL, DMODEL);
}

// round 14
// speedup vs baseline: 1.0248x; 1.0248x over previous
#include <cuda_runtime.h>
#include <cuda_fp16.h>
#include <cstdint>
#include <cstddef>

#define BATCH   2
#define SEQLEN  4096
#define DMODEL  512
#define DINNER  1024
#define NH      16
#define HD      64
#define DSTATE  64
#define CONVDIM 1152
#define DPROJ   2192
#define NPOS    (BATCH * SEQLEN)   // 8192
#define NC      64
#define CS      64
#define EPSV    1e-5f
#define NPAD1   2304

// ---------------- scratch (static device globals) ---------------------------
__device__ float  g_zx [(size_t)NPOS * DPROJ];
__device__ __half g_xbc[(size_t)NPOS * CONVDIM];
__device__ float  g_dt [NPOS * NH];
__device__ float  g_cl [BATCH * NH * SEQLEN];
__device__ float  g_S  [(size_t)BATCH * NH * NC * HD * DSTATE];
__device__ __half g_Sh [(size_t)BATCH * NH * NC * HD * DSTATE];
__device__ float  g_y  [(size_t)NPOS * DINNER];

__device__ __half g_xh [(size_t)NPOS * DMODEL];
__device__ __half g_w1h[(size_t)NPAD1 * DMODEL];
__device__ __half g_yh [(size_t)NPOS * DINNER];
__device__ __half g_w2h[(size_t)DMODEL * DINNER];

// ---------------- PTX helpers ------------------------------------------------
__device__ __forceinline__ uint32_t smem_u32(const void* p) {
  uint32_t a;
  asm("{ .reg .u64 t; cvta.to.shared.u64 t, %1; cvt.u32.u64 %0, t; }" : "=r"(a) : "l"(p));
  return a;
}
__device__ __forceinline__ void ldm4(uint32_t* r, uint32_t addr) {
  asm volatile("ldmatrix.sync.aligned.m8n8.x4.shared.b16 {%0,%1,%2,%3}, [%4];"
               : "=r"(r[0]), "=r"(r[1]), "=r"(r[2]), "=r"(r[3]) : "r"(addr));
}
__device__ __forceinline__ void ldm4t(uint32_t* r, uint32_t addr) {
  asm volatile("ldmatrix.sync.aligned.m8n8.x4.trans.shared.b16 {%0,%1,%2,%3}, [%4];"
               : "=r"(r[0]), "=r"(r[1]), "=r"(r[2]), "=r"(r[3]) : "r"(addr));
}
__device__ __forceinline__ void mma16816(float* c, const uint32_t* a, const uint32_t* b) {
  asm volatile(
      "mma.sync.aligned.m16n8k16.row.col.f32.f16.f16.f32 "
      "{%0,%1,%2,%3}, {%4,%5,%6,%7}, {%8,%9}, {%0,%1,%2,%3};"
      : "+f"(c[0]), "+f"(c[1]), "+f"(c[2]), "+f"(c[3])
      : "r"(a[0]), "r"(a[1]), "r"(a[2]), "r"(a[3]), "r"(b[0]), "r"(b[1]));
}
#define CPASYNC(dst, src) \
  asm volatile("cp.async.cg.shared.global [%0], [%1], 16;" :: "r"(dst), "l"(src))
#define CPCOMMIT() asm volatile("cp.async.commit_group;" ::: "memory")
#define CPWAIT(n)  asm volatile("cp.async.wait_group %0;" :: "n"(n) : "memory")
#define SWZ(off)   ((off) ^ (((off) >> 3) & 0x70))

// ---------------- HMMA GEMM (fp16): C = A @ B^T ------------------------------
#define SM_BUF   32768
#define SM_TOTAL (3 * SM_BUF)

__global__ __launch_bounds__(128, 2) void gemm_tc(
    const __half* __restrict__ A, const __half* __restrict__ B,
    float* __restrict__ C, int K, int N, int ldc) {
  extern __shared__ char smem[];
  const uint32_t sb = smem_u32(smem);
  const int tid = threadIdx.x, wid = tid >> 5, lane = tid & 31;
  const int bm = blockIdx.y * 128, bn = blockIdx.x * 128;
  const int wrow = wid & 1, wcol = wid >> 1;

  float acc[4][8][4];
  #pragma unroll
  for (int i = 0; i < 4; i++)
    #pragma unroll
    for (int j = 0; j < 8; j++)
      #pragma unroll
      for (int v = 0; v < 4; v++) acc[i][j][v] = 0.f;

  const int nK = K >> 6;

  #pragma unroll
  for (int pre = 0; pre < 2; pre++) {
    if (pre < nK) {
      const int k0 = pre << 6;
      const uint32_t bbuf = sb + pre * SM_BUF;
      #pragma unroll
      for (int it = 0; it < 16; it++) {
        const int u = it * 128 + tid;
        const int tile = u >> 10, idx = u & 1023;
        const int row = idx >> 3, c16 = idx & 7;
        const uint32_t dst = bbuf + tile * 16384 + SWZ((uint32_t)(row * 128 + c16 * 16));
        const __half* src = (tile == 0) ? A + (size_t)(bm + row) * K + k0 + c16 * 8
                                        : B + (size_t)(bn + row) * K + k0 + c16 * 8;
        CPASYNC(dst, src);
      }
    }
    CPCOMMIT();
  }

  int buf = 0;
  for (int i = 0; i < nK; i++) {
    if (i + 2 < nK) {
      const int k0 = (i + 2) << 6;
      const uint32_t bbuf = sb + ((buf + 2 >= 3) ? buf - 1 : buf + 2) * SM_BUF;
      #pragma unroll
      for (int it = 0; it < 16; it++) {
        const int u = it * 128 + tid;
        const int tile = u >> 10, idx = u & 1023;
        const int row = idx >> 3, c16 = idx & 7;
        const uint32_t dst = bbuf + tile * 16384 + SWZ((uint32_t)(row * 128 + c16 * 16));
        const __half* src = (tile == 0) ? A + (size_t)(bm + row) * K + k0 + c16 * 8
                                        : B + (size_t)(bn + row) * K + k0 + c16 * 8;
        CPASYNC(dst, src);
      }
    }
    CPCOMMIT();
    CPWAIT(2);
    __syncthreads();

    const uint32_t tb = sb + buf * SM_BUF;
    const int arow = wrow * 64 + (lane & 15);
    const int brow = wcol * 64 + (lane & 7) + ((lane >> 4) & 1) * 8;
    const int akb  = (lane >> 4) * 16;
    const int bkb  = ((lane >> 3) & 1) * 16;

    #pragma unroll
    for (int ks = 0; ks < 4; ks++) {
      uint32_t ah[4][4];
      #pragma unroll
      for (int mt = 0; mt < 4; mt++) {
        const uint32_t off = SWZ((uint32_t)((arow + mt * 16) * 128 + ks * 32 + akb));
        ldm4(ah[mt], tb + off);
      }
      #pragma unroll
      for (int p = 0; p < 4; p++) {
        uint32_t bf[4];
        const uint32_t off = SWZ((uint32_t)((brow + p * 16) * 128 + ks * 32 + bkb));
        ldm4(bf, tb + 16384 + off);
        #pragma unroll
        for (int mt = 0; mt < 4; mt++) {
          mma16816(acc[mt][2 * p],     ah[mt], &bf[0]);
          mma16816(acc[mt][2 * p + 1], ah[mt], &bf[2]);
        }
      }
    }
    __syncthreads();
    buf = (buf + 1 >= 3) ? 0 : buf + 1;
  }

  const int r0 = bm + wrow * 64 + (lane >> 2);
  const int c0 = bn + wcol * 64 + (lane & 3) * 2;
  #pragma unroll
  for (int mt = 0; mt < 4; mt++)
    #pragma unroll
    for (int nt = 0; nt < 8; nt++) {
      const int col = c0 + nt * 8;
      if (col < N) {
        const int row = r0 + mt * 16;
        *(float2*)&C[(size_t)row * ldc + col] =
            make_float2(acc[mt][nt][0], acc[mt][nt][1]);
        *(float2*)&C[(size_t)(row + 8) * ldc + col] =
            make_float2(acc[mt][nt][2], acc[mt][nt][3]);
      }
    }
}

// ---------------- fused prep: x->fp16 cast + both W transposes ---------------
// seg A: blocks [0, 16384)               tofp16 of x
// seg B: blocks [16384, 16384+1152)      wtrans W_in  -> g_w1h [NPAD1][DMODEL]
// seg C: blocks [17536, 17536+512)       wtrans W_out -> g_w2h [DMODEL][DINNER]
#define PREP_A 16384
#define PREP_B 1152
#define PREP_C 512

__global__ __launch_bounds__(256) void prep_kernel(
    const float* __restrict__ x, const float* __restrict__ W_in,
    const float* __restrict__ W_out) {
  __shared__ float t[32][33];
  const int bid = blockIdx.x, tid = threadIdx.x;
  if (bid < PREP_A) {
    const int i = bid * 256 + tid;
    g_xh[i] = __float2half(x[i]);
    return;
  }
  const float* W;
  __half* th;
  int K, N, bx, by;
  if (bid < PREP_A + PREP_B) {
    const int lb = bid - PREP_A;
    W = W_in; th = g_w1h; K = DMODEL; N = DPROJ;
    bx = lb % (NPAD1 / 32); by = lb / (NPAD1 / 32);
  } else {
    const int lb = bid - PREP_A - PREP_B;
    W = W_out; th = g_w2h; K = DINNER; N = DMODEL;
    bx = lb % (DMODEL / 32); by = lb / (DMODEL / 32);
  }
  const int n0 = bx * 32, k0 = by * 32;
  const int tx = tid & 31, ty = tid >> 5;
  #pragma unroll
  for (int r = 0; r < 4; r++) {
    int k = k0 + ty + r * 8, n = n0 + tx;
    t[ty + r * 8][tx] = (n < N) ? W[(size_t)k * N + n] : 0.f;
  }
  __syncthreads();
  #pragma unroll
  for (int r = 0; r < 4; r++) {
    int n = n0 + ty + r * 8, k = k0 + tx;
    th[(size_t)n * K + k] = __float2half(t[tx][ty + r * 8]);
  }
}

// ---------------- fused conv+silu and dt+cumlog ------------------------------
// blocks [0, 9216): conv (128 threads, ch-block = bid%9, grp = bid/9)
// blocks [9216, 9728): dtscan (4 warps each -> 2048 warps total)
#define CONV_BLKS 9216

__global__ __launch_bounds__(128) void convdt_kernel(
    const float* __restrict__ cw, const float* __restrict__ cb,
    const float* __restrict__ dtb, const float* __restrict__ alog) {
  const int bid = blockIdx.x, tid = threadIdx.x;
  if (bid < CONV_BLKS) {
    const int ch  = (bid % 9) * 128 + tid;
    const int grp = bid / 9;
    const size_t pos0 = (size_t)grp * 8;
    const int l0 = (int)(pos0 & (SEQLEN - 1));
    const float* src = g_zx + pos0 * DPROJ + DINNER + ch;
    const float w0 = cw[ch * 4 + 0], w1 = cw[ch * 4 + 1];
    const float w2 = cw[ch * 4 + 2], w3 = cw[ch * 4 + 3];
    const float bias = cb[ch];
    float v[11];
    #pragma unroll
    for (int j = 0; j < 3; j++)
      v[j] = (l0 >= 3 - j) ? src[(ptrdiff_t)(j - 3) * DPROJ] : 0.f;
    #pragma unroll
    for (int j = 0; j < 8; j++)
      v[3 + j] = src[(ptrdiff_t)j * DPROJ];
    __half* dst = g_xbc + pos0 * CONVDIM + ch;
    #pragma unroll
    for (int j = 0; j < 8; j++) {
      float a = bias + w0 * v[j] + w1 * v[j + 1] + w2 * v[j + 2] + w3 * v[j + 3];
      dst[(size_t)j * CONVDIM] = __float2half(a / (1.f + __expf(-a)));
    }
    return;
  }
  // dtscan segment
  const int gw = ((bid - CONV_BLKS) * 128 + tid) >> 5;   // 0..2047
  const int lane = tid & 31;
  const int c = gw & (NC - 1);
  const int bh = gw >> 6;
  const int b = bh >> 4, h = bh & (NH - 1);
  const int t0 = c * CS;
  const int pos0 = b * SEQLEN + t0 + lane;
  const float bsh = dtb[h];
  const float A = -expf(alog[h]);
  float v0 = g_zx[(size_t)pos0 * DPROJ + DINNER + CONVDIM + h] + bsh;
  float v1 = g_zx[(size_t)(pos0 + 32) * DPROJ + DINNER + CONVDIM + h] + bsh;
  float sp0 = (v0 > 20.f) ? v0 : log1pf(expf(v0));
  float sp1 = (v1 > 20.f) ? v1 : log1pf(expf(v1));
  g_dt[pos0 * NH + h] = sp0;
  g_dt[(pos0 + 32) * NH + h] = sp1;
  float x0 = A * sp0, x1 = A * sp1;
  #pragma unroll
  for (int o = 1; o < 32; o <<= 1) {
    float t = __shfl_up_sync(0xFFFFFFFFu, x0, o);
    if (lane >= o) x0 += t;
  }
  float tot0 = __shfl_sync(0xFFFFFFFFu, x0, 31);
  #pragma unroll
  for (int o = 1; o < 32; o <<= 1) {
    float t = __shfl_up_sync(0xFFFFFFFFu, x1, o);
    if (lane >= o) x1 += t;
  }
  x1 += tot0;
  g_cl[bh * SEQLEN + t0 + lane] = x0;
  g_cl[bh * SEQLEN + t0 + 32 + lane] = x1;
}

// ---------------- intra-chunk SSD kernel (HMMA, trans-ldmatrix) --------------
#define CLDH 72
#define CLDB 144
#define CH_SMEM (5 * 9216 + 128 * 4)

__global__ __launch_bounds__(256) void chunk_kernel(const float* __restrict__ Dv) {
  extern __shared__ __align__(16) __half sh[];
  __half* sC  = sh;            // [64][72] C[t][n]
  __half* sB  = sh + 4608;     // [64][72] B[s][n]
  __half* sX  = sh + 9216;     // [64][72] X[s][p]
  __half* sM  = sh + 13824;    // [64][72] M[t][s]
  __half* sXW = sh + 18432;    // [64][72] XW[s][p]
  float* scl = (float*)(sh + 23040);
  float* sdt = scl + 64;

  const int bid = blockIdx.x;
  const int c = bid & (NC - 1);
  const int bh = bid >> 6;
  const int h = bh & (NH - 1);
  const int b = bh >> 4;
  const int tid = threadIdx.x;
  const int t0 = c * CS;
  const int wid = tid >> 5, lane = tid & 31;

  {
    const int row = tid >> 2, cs = (tid & 3) * 16;
    const __half* base = g_xbc + (size_t)(b * SEQLEN + t0 + row) * CONVDIM;
    #pragma unroll
    for (int q = 0; q < 2; q++) {
      const int col = cs + q * 8;
      *(uint4*)(sB + row * CLDH + col) = *(const uint4*)(base + DINNER + col);
      *(uint4*)(sC + row * CLDH + col) = *(const uint4*)(base + DINNER + DSTATE + col);
      *(uint4*)(sX + row * CLDH + col) = *(const uint4*)(base + h * HD + col);
    }
    if (tid < 64) {
      scl[tid] = g_cl[bh * SEQLEN + t0 + tid];
      sdt[tid] = g_dt[(b * SEQLEN + t0 + tid) * NH + h];
    }
  }
  __syncthreads();

  const uint32_t uC = smem_u32(sC), uB = smem_u32(sB), uX = smem_u32(sX);
  const uint32_t uM = smem_u32(sM), uXW = smem_u32(sXW);
  const int mt0 = (wid & 3) * 16;
  const int nt0 = (wid >> 2) * 32;
  const int aoff = (lane & 15) * CLDB + (lane >> 4) * 16;
  const int boff = ((lane & 7) + ((lane >> 4) & 1) * 8) * CLDB + ((lane >> 3) & 1) * 16;
  const int bofft_row = (lane & 7) + ((lane >> 3) & 1) * 8;
  const int bofft_b   = ((lane >> 4) & 1) * 16;
  const int aofft_row = (lane & 7) + ((lane >> 4) & 1) * 8;
  const int aofft_b   = ((lane >> 3) & 1) * 16;
  const int rb = mt0 + (lane >> 2);
  const int cb = nt0 + (lane & 3) * 2;

  float acc[4][4];

  // ---- GEMM1: M0 = C @ B^T ----
  #pragma unroll
  for (int nt = 0; nt < 4; nt++)
    #pragma unroll
    for (int v = 0; v < 4; v++) acc[nt][v] = 0.f;
  #pragma unroll
  for (int ks = 0; ks < 4; ks++) {
    uint32_t af[4];
    ldm4(af, uC + (uint32_t)(mt0 * CLDB + aoff + ks * 32));
    #pragma unroll
    for (int p = 0; p < 2; p++) {
      uint32_t bf[4];
      ldm4(bf, uB + (uint32_t)((nt0 + p * 16) * CLDB + boff + ks * 32));
      mma16816(acc[2 * p],     af, &bf[0]);
      mma16816(acc[2 * p + 1], af, &bf[2]);
    }
  }
  #pragma unroll
  for (int nt = 0; nt < 4; nt++)
    #pragma unroll
    for (int cc = 0; cc < 4; cc++) {
      const int t = rb + ((cc >> 1) << 3);
      const int s = cb + nt * 8 + (cc & 1);
      float v = acc[nt][cc];
      v = (s <= t) ? v * __expf(scl[t] - scl[s]) * sdt[s] : 0.f;
      sM[t * CLDH + s] = __float2half(v);
    }
  {
    const float Ltot = scl[63];
    const int row = tid >> 2, cs = (tid & 3) * 16;
    const float w = __expf(Ltot - scl[row]) * sdt[row];
    #pragma unroll
    for (int j = 0; j < 16; j++) {
      const int o = row * CLDH + cs + j;
      sXW[o] = __float2half(__half2float(sX[o]) * w);
    }
  }
  __syncthreads();

  // ---- GEMM2: Y = M @ X ----
  #pragma unroll
  for (int nt = 0; nt < 4; nt++)
    #pragma unroll
    for (int v = 0; v < 4; v++) acc[nt][v] = 0.f;
  #pragma unroll
  for (int ks = 0; ks < 4; ks++) {
    uint32_t af[4];
    ldm4(af, uM + (uint32_t)(mt0 * CLDB + aoff + ks * 32));
    #pragma unroll
    for (int p = 0; p < 2; p++) {
      uint32_t bf[4];
      ldm4t(bf, uX + (uint32_t)((ks * 16 + bofft_row) * CLDB
                                + (nt0 + p * 16) * 2 + bofft_b));
      mma16816(acc[2 * p],     af, &bf[0]);
      mma16816(acc[2 * p + 1], af, &bf[2]);
    }
  }
  {
    const float Dh = Dv[h];
    #pragma unroll
    for (int nt = 0; nt < 4; nt++) {
      const int p = cb + nt * 8;
      const int t1 = rb, t2 = rb + 8;
      float2 o01 = make_float2(
          acc[nt][0] + Dh * __half2float(sX[t1 * CLDH + p]),
          acc[nt][1] + Dh * __half2float(sX[t1 * CLDH + p + 1]));
      float2 o23 = make_float2(
          acc[nt][2] + Dh * __half2float(sX[t2 * CLDH + p]),
          acc[nt][3] + Dh * __half2float(sX[t2 * CLDH + p + 1]));
      *(float2*)&g_y[(size_t)(b * SEQLEN + t0 + t1) * DINNER + h * HD + p] = o01;
      *(float2*)&g_y[(size_t)(b * SEQLEN + t0 + t2) * DINNER + h * HD + p] = o23;
    }
  }

  // ---- GEMM3: S = XW^T @ B ----
  #pragma unroll
  for (int nt = 0; nt < 4; nt++)
    #pragma unroll
    for (int v = 0; v < 4; v++) acc[nt][v] = 0.f;
  #pragma unroll
  for (int ks = 0; ks < 4; ks++) {
    uint32_t af[4];
    ldm4t(af, uXW + (uint32_t)((ks * 16 + aofft_row) * CLDB + mt0 * 2 + aofft_b));
    #pragma unroll
    for (int p = 0; p < 2; p++) {
      uint32_t bf[4];
      ldm4t(bf, uB + (uint32_t)((ks * 16 + bofft_row) * CLDB
                                + (nt0 + p * 16) * 2 + bofft_b));
      mma16816(acc[2 * p],     af, &bf[0]);
      mma16816(acc[2 * p + 1], af, &bf[2]);
    }
  }
  #pragma unroll
  for (int nt = 0; nt < 4; nt++) {
    const int n = cb + nt * 8;
    *(float2*)&g_S[(size_t)bid * 4096 + rb * 64 + n] =
        make_float2(acc[nt][0], acc[nt][1]);
    *(float2*)&g_S[(size_t)bid * 4096 + (rb + 8) * 64 + n] =
        make_float2(acc[nt][2], acc[nt][3]);
  }
}

// ---------------- inter-chunk state scan (fp32 in, fp16 prefix out) ---------
__global__ __launch_bounds__(128) void scan_kernel() {
  const int bh = blockIdx.x;
  const int slice = blockIdx.y;
  const int tid = threadIdx.x;
  const int off = slice * 512 + tid * 4;
  float run[4] = {0.f, 0.f, 0.f, 0.f};
  for (int c = 0; c < NC; c++) {
    float a = __expf(g_cl[bh * SEQLEN + c * CS + CS - 1]);
    const float* p = g_S + (size_t)(bh * NC + c) * 4096 + off;
    float4 v = *(const float4*)p;
    __half2* d = (__half2*)(g_Sh + (size_t)(bh * NC + c) * 4096 + off);
    d[0] = __floats2half2_rn(run[0], run[1]);
    d[1] = __floats2half2_rn(run[2], run[3]);
    run[0] = a * run[0] + v.x;
    run[1] = a * run[1] + v.y;
    run[2] = a * run[2] + v.z;
    run[3] = a * run[3] + v.w;
  }
}

// ---------------- inter-chunk contribution (HMMA fp16) ----------------------
__global__ __launch_bounds__(256) void inter_kernel() {
  __shared__ __align__(16) __half sC[4608];
  __shared__ __align__(16) __half sS[4608];
  __shared__ float scl[64];
  const int bid = blockIdx.x;
  const int c = bid & (NC - 1);
  const int bh = bid >> 6;
  const int h = bh & (NH - 1);
  const int b = bh >> 4;
  const int tid = threadIdx.x;
  const int t0 = c * CS;
  const int wid = tid >> 5, lane = tid & 31;

  {
    const int row = tid >> 2, cs = (tid & 3) * 16;
    const __half* cbase = g_xbc + (size_t)(b * SEQLEN + t0 + row) * CONVDIM
                          + DINNER + DSTATE;
    #pragma unroll
    for (int q = 0; q < 2; q++) {
      *(uint4*)(sC + row * CLDH + cs + q * 8) = *(const uint4*)(cbase + cs + q * 8);
      *(uint4*)(sS + row * CLDH + cs + q * 8) =
          *(const uint4*)(g_Sh + (size_t)bid * 4096 + row * 64 + cs + q * 8);
    }
    if (tid < 64) scl[tid] = g_cl[bh * SEQLEN + t0 + tid];
  }
  __syncthreads();

  const uint32_t uC = smem_u32(sC), uS = smem_u32(sS);
  const int mt0 = (wid & 3) * 16;
  const int nt0 = (wid >> 2) * 32;
  const int aoff = (lane & 15) * CLDB + (lane >> 4) * 16;
  const int boff = ((lane & 7) + ((lane >> 4) & 1) * 8) * CLDB + ((lane >> 3) & 1) * 16;
  const int rb = mt0 + (lane >> 2);
  const int cb = nt0 + (lane & 3) * 2;

  float acc[4][4];
  #pragma unroll
  for (int nt = 0; nt < 4; nt++)
    #pragma unroll
    for (int v = 0; v < 4; v++) acc[nt][v] = 0.f;
  #pragma unroll
  for (int ks = 0; ks < 4; ks++) {
    uint32_t af[4];
    ldm4(af, uC + (uint32_t)(mt0 * CLDB + aoff + ks * 32));
    #pragma unroll
    for (int p = 0; p < 2; p++) {
      uint32_t bf[4];
      ldm4(bf, uS + (uint32_t)((nt0 + p * 16) * CLDB + boff + ks * 32));
      mma16816(acc[2 * p],     af, &bf[0]);
      mma16816(acc[2 * p + 1], af, &bf[2]);
    }
  }
  const float e1 = __expf(scl[rb]);
  const float e2 = __expf(scl[rb + 8]);
  #pragma unroll
  for (int nt = 0; nt < 4; nt++) {
    const int p = cb + nt * 8;
    size_t o1 = (size_t)(b * SEQLEN + t0 + rb) * DINNER + h * HD + p;
    size_t o2 = (size_t)(b * SEQLEN + t0 + rb + 8) * DINNER + h * HD + p;
    float2 c1 = *(float2*)&g_y[o1];
    float2 c2 = *(float2*)&g_y[o2];
    c1.x += e1 * acc[nt][0]; c1.y += e1 * acc[nt][1];
    c2.x += e2 * acc[nt][2]; c2.y += e2 * acc[nt][3];
    *(float2*)&g_y[o1] = c1;
    *(float2*)&g_y[o2] = c2;
  }
}

// ---------------- gate + RMSNorm, emits fp16 ---------------------------------
__global__ __launch_bounds__(256) void norm_kernel(const float* __restrict__ nw) {
  const int pos = blockIdx.x, tid = threadIdx.x;
  float4 yv = *(const float4*)(g_y  + (size_t)pos * DINNER + tid * 4);
  float4 zv = *(const float4*)(g_zx + (size_t)pos * DPROJ  + tid * 4);
  float4 g;
  g.x = yv.x * (zv.x / (1.f + __expf(-zv.x)));
  g.y = yv.y * (zv.y / (1.f + __expf(-zv.y)));
  g.z = yv.z * (zv.z / (1.f + __expf(-zv.z)));
  g.w = yv.w * (zv.w / (1.f + __expf(-zv.w)));
  float ssq = g.x * g.x + g.y * g.y + g.z * g.z + g.w * g.w;
  #pragma unroll
  for (int o = 16; o; o >>= 1) ssq += __shfl_xor_sync(0xFFFFFFFFu, ssq, o);
  __shared__ float red[8];
  if ((tid & 31) == 0) red[tid >> 5] = ssq;
  __syncthreads();
  float tot = red[0] + red[1] + red[2] + red[3] + red[4] + red[5] + red[6] + red[7];
  float scale = rsqrtf(tot * (1.f / DINNER) + EPSV);
  float4 w = *(const float4*)(nw + tid * 4);
  __half2* dst = (__half2*)(g_yh + (size_t)pos * DINNER + tid * 4);
  dst[0] = __floats2half2_rn(g.x * scale * w.x, g.y * scale * w.y);
  dst[1] = __floats2half2_rn(g.z * scale * w.z, g.w * scale * w.w);
}

// ---------------- launch ------------------------------------------------------
extern "C" void kernel_launch(void* const* d_in, const int* in_sizes, int n_in,
                              void* d_out, int out_size) {
  const float* x       = (const float*)d_in[0];
  const float* W_in    = (const float*)d_in[1];
  const float* conv_w  = (const float*)d_in[2];
  const float* conv_b  = (const float*)d_in[3];
  const float* dt_bias = (const float*)d_in[4];
  const float* A_log   = (const float*)d_in[5];
  const float* Dv      = (const float*)d_in[6];
  const float* nw      = (const float*)d_in[7];
  const float* W_out   = (const float*)d_in[8];
  float* out = (float*)d_out;

  void* p;
  cudaGetSymbolAddress(&p, g_zx);  float* zx = (float*)p;
  cudaGetSymbolAddress(&p, g_xh);  __half* xh  = (__half*)p;
  cudaGetSymbolAddress(&p, g_w1h); __half* w1h = (__half*)p;
  cudaGetSymbolAddress(&p, g_yh);  __half* yh  = (__half*)p;
  cudaGetSymbolAddress(&p, g_w2h); __half* w2h = (__half*)p;

  cudaFuncSetAttribute(chunk_kernel, cudaFuncAttributeMaxDynamicSharedMemorySize, CH_SMEM);
  cudaFuncSetAttribute(gemm_tc, cudaFuncAttributeMaxDynamicSharedMemorySize, SM_TOTAL);

  dim3 blk(256);
  // 0) fused prep: x cast + both W transposes
  prep_kernel<<<PREP_A + PREP_B + PREP_C, blk>>>(x, W_in, W_out);
  // 1) in-projection
  gemm_tc<<<dim3(NPAD1 / 128, NPOS / 128), dim3(128), SM_TOTAL>>>(xh, w1h, zx,
                                                                  DMODEL, DPROJ, DPROJ);
  // 2) fused conv+silu and dt+cumlog
  convdt_kernel<<<CONV_BLKS + 512, dim3(128)>>>(conv_w, conv_b, dt_bias, A_log);
  // 3) intra-chunk SSD (HMMA, trans-ldmatrix)
  chunk_kernel<<<BATCH * NH * NC, blk, CH_SMEM>>>(Dv);
  // 4) inter-chunk state scan
  scan_kernel<<<dim3(BATCH * NH, 8), dim3(128)>>>();
  // 5) inter-chunk correction (HMMA)
  inter_kernel<<<BATCH * NH * NC, blk>>>();
  // 6) gate + RMSNorm
  norm_kernel<<<NPOS, blk>>>(nw);
  // 7) out-projection
  gemm_tc<<<dim3(DMODEL / 128, NPOS / 128), dim3(128), SM_TOTAL>>>(yh, w2h, out,
                                                                   DINNER, DMODEL, DMODEL);
}

// round 15
// speedup vs baseline: 1.0341x; 1.0091x over previous
#include <cuda_runtime.h>
#include <cuda_fp16.h>
#include <cstdint>
#include <cstddef>

#define BATCH   2
#define SEQLEN  4096
#define DMODEL  512
#define DINNER  1024
#define NH      16
#define HD      64
#define DSTATE  64
#define CONVDIM 1152
#define DPROJ   2192
#define NPOS    (BATCH * SEQLEN)   // 8192
#define NC      64
#define CS      64
#define EPSV    1e-5f
#define NPAD1   2304

// ---------------- scratch (static device globals) ---------------------------
__device__ float  g_zx [(size_t)NPOS * DPROJ];
__device__ __half g_xbc[(size_t)NPOS * CONVDIM];
__device__ float  g_dt [NPOS * NH];
__device__ float  g_cl [BATCH * NH * SEQLEN];
__device__ float  g_S  [(size_t)BATCH * NH * NC * HD * DSTATE];
__device__ __half g_Sh [(size_t)BATCH * NH * NC * HD * DSTATE];
__device__ float  g_y  [(size_t)NPOS * DINNER];

__device__ __half g_xh [(size_t)NPOS * DMODEL];
__device__ __half g_w1h[(size_t)NPAD1 * DMODEL];
__device__ __half g_yh [(size_t)NPOS * DINNER];
__device__ __half g_w2h[(size_t)DMODEL * DINNER];

// ---------------- PTX helpers ------------------------------------------------
__device__ __forceinline__ uint32_t smem_u32(const void* p) {
  uint32_t a;
  asm("{ .reg .u64 t; cvta.to.shared.u64 t, %1; cvt.u32.u64 %0, t; }" : "=r"(a) : "l"(p));
  return a;
}
__device__ __forceinline__ void ldm4(uint32_t* r, uint32_t addr) {
  asm volatile("ldmatrix.sync.aligned.m8n8.x4.shared.b16 {%0,%1,%2,%3}, [%4];"
               : "=r"(r[0]), "=r"(r[1]), "=r"(r[2]), "=r"(r[3]) : "r"(addr));
}
__device__ __forceinline__ void ldm4t(uint32_t* r, uint32_t addr) {
  asm volatile("ldmatrix.sync.aligned.m8n8.x4.trans.shared.b16 {%0,%1,%2,%3}, [%4];"
               : "=r"(r[0]), "=r"(r[1]), "=r"(r[2]), "=r"(r[3]) : "r"(addr));
}
__device__ __forceinline__ void mma16816(float* c, const uint32_t* a, const uint32_t* b) {
  asm volatile(
      "mma.sync.aligned.m16n8k16.row.col.f32.f16.f16.f32 "
      "{%0,%1,%2,%3}, {%4,%5,%6,%7}, {%8,%9}, {%0,%1,%2,%3};"
      : "+f"(c[0]), "+f"(c[1]), "+f"(c[2]), "+f"(c[3])
      : "r"(a[0]), "r"(a[1]), "r"(a[2]), "r"(a[3]), "r"(b[0]), "r"(b[1]));
}
#define CPASYNC(dst, src) \
  asm volatile("cp.async.cg.shared.global [%0], [%1], 16;" :: "r"(dst), "l"(src))
#define CPCOMMIT() asm volatile("cp.async.commit_group;" ::: "memory")
#define CPWAIT(n)  asm volatile("cp.async.wait_group %0;" :: "n"(n) : "memory")
#define SWZ(off)   ((off) ^ (((off) >> 3) & 0x70))

// ---------------- HMMA GEMM (fp16): C = A @ B^T ------------------------------
#define SM_BUF   32768
#define SM_TOTAL (3 * SM_BUF)

__global__ __launch_bounds__(128, 2) void gemm_tc(
    const __half* __restrict__ A, const __half* __restrict__ B,
    float* __restrict__ C, int K, int N, int ldc) {
  extern __shared__ char smem[];
  const uint32_t sb = smem_u32(smem);
  const int tid = threadIdx.x, wid = tid >> 5, lane = tid & 31;
  const int bm = blockIdx.y * 128, bn = blockIdx.x * 128;
  const int wrow = wid & 1, wcol = wid >> 1;

  float acc[4][8][4];
  #pragma unroll
  for (int i = 0; i < 4; i++)
    #pragma unroll
    for (int j = 0; j < 8; j++)
      #pragma unroll
      for (int v = 0; v < 4; v++) acc[i][j][v] = 0.f;

  const int nK = K >> 6;

  #pragma unroll
  for (int pre = 0; pre < 2; pre++) {
    if (pre < nK) {
      const int k0 = pre << 6;
      const uint32_t bbuf = sb + pre * SM_BUF;
      #pragma unroll
      for (int it = 0; it < 16; it++) {
        const int u = it * 128 + tid;
        const int tile = u >> 10, idx = u & 1023;
        const int row = idx >> 3, c16 = idx & 7;
        const uint32_t dst = bbuf + tile * 16384 + SWZ((uint32_t)(row * 128 + c16 * 16));
        const __half* src = (tile == 0) ? A + (size_t)(bm + row) * K + k0 + c16 * 8
                                        : B + (size_t)(bn + row) * K + k0 + c16 * 8;
        CPASYNC(dst, src);
      }
    }
    CPCOMMIT();
  }

  int buf = 0;
  for (int i = 0; i < nK; i++) {
    if (i + 2 < nK) {
      const int k0 = (i + 2) << 6;
      const uint32_t bbuf = sb + ((buf + 2 >= 3) ? buf - 1 : buf + 2) * SM_BUF;
      #pragma unroll
      for (int it = 0; it < 16; it++) {
        const int u = it * 128 + tid;
        const int tile = u >> 10, idx = u & 1023;
        const int row = idx >> 3, c16 = idx & 7;
        const uint32_t dst = bbuf + tile * 16384 + SWZ((uint32_t)(row * 128 + c16 * 16));
        const __half* src = (tile == 0) ? A + (size_t)(bm + row) * K + k0 + c16 * 8
                                        : B + (size_t)(bn + row) * K + k0 + c16 * 8;
        CPASYNC(dst, src);
      }
    }
    CPCOMMIT();
    CPWAIT(2);
    __syncthreads();

    const uint32_t tb = sb + buf * SM_BUF;
    const int arow = wrow * 64 + (lane & 15);
    const int brow = wcol * 64 + (lane & 7) + ((lane >> 4) & 1) * 8;
    const int akb  = (lane >> 4) * 16;
    const int bkb  = ((lane >> 3) & 1) * 16;

    #pragma unroll
    for (int ks = 0; ks < 4; ks++) {
      uint32_t ah[4][4];
      #pragma unroll
      for (int mt = 0; mt < 4; mt++) {
        const uint32_t off = SWZ((uint32_t)((arow + mt * 16) * 128 + ks * 32 + akb));
        ldm4(ah[mt], tb + off);
      }
      #pragma unroll
      for (int p = 0; p < 4; p++) {
        uint32_t bf[4];
        const uint32_t off = SWZ((uint32_t)((brow + p * 16) * 128 + ks * 32 + bkb));
        ldm4(bf, tb + 16384 + off);
        #pragma unroll
        for (int mt = 0; mt < 4; mt++) {
          mma16816(acc[mt][2 * p],     ah[mt], &bf[0]);
          mma16816(acc[mt][2 * p + 1], ah[mt], &bf[2]);
        }
      }
    }
    __syncthreads();
    buf = (buf + 1 >= 3) ? 0 : buf + 1;
  }

  const int r0 = bm + wrow * 64 + (lane >> 2);
  const int c0 = bn + wcol * 64 + (lane & 3) * 2;
  #pragma unroll
  for (int mt = 0; mt < 4; mt++)
    #pragma unroll
    for (int nt = 0; nt < 8; nt++) {
      const int col = c0 + nt * 8;
      if (col < N) {
        const int row = r0 + mt * 16;
        *(float2*)&C[(size_t)row * ldc + col] =
            make_float2(acc[mt][nt][0], acc[mt][nt][1]);
        *(float2*)&C[(size_t)(row + 8) * ldc + col] =
            make_float2(acc[mt][nt][2], acc[mt][nt][3]);
      }
    }
}

// ---------------- fused prep: x->fp16 cast + both W transposes ---------------
#define PREP_A 16384
#define PREP_B 1152
#define PREP_C 512

__global__ __launch_bounds__(256) void prep_kernel(
    const float* __restrict__ x, const float* __restrict__ W_in,
    const float* __restrict__ W_out) {
  __shared__ float t[32][33];
  const int bid = blockIdx.x, tid = threadIdx.x;
  if (bid < PREP_A) {
    const int i = bid * 256 + tid;
    g_xh[i] = __float2half(x[i]);
    return;
  }
  const float* W;
  __half* th;
  int K, N, bx, by;
  if (bid < PREP_A + PREP_B) {
    const int lb = bid - PREP_A;
    W = W_in; th = g_w1h; K = DMODEL; N = DPROJ;
    bx = lb % (NPAD1 / 32); by = lb / (NPAD1 / 32);
  } else {
    const int lb = bid - PREP_A - PREP_B;
    W = W_out; th = g_w2h; K = DINNER; N = DMODEL;
    bx = lb % (DMODEL / 32); by = lb / (DMODEL / 32);
  }
  const int n0 = bx * 32, k0 = by * 32;
  const int tx = tid & 31, ty = tid >> 5;
  #pragma unroll
  for (int r = 0; r < 4; r++) {
    int k = k0 + ty + r * 8, n = n0 + tx;
    t[ty + r * 8][tx] = (n < N) ? W[(size_t)k * N + n] : 0.f;
  }
  __syncthreads();
  #pragma unroll
  for (int r = 0; r < 4; r++) {
    int n = n0 + ty + r * 8, k = k0 + tx;
    th[(size_t)n * K + k] = __float2half(t[tx][ty + r * 8]);
  }
}

// ---------------- fused conv+silu and dt+cumlog ------------------------------
#define CONV_BLKS 9216

__global__ __launch_bounds__(128) void convdt_kernel(
    const float* __restrict__ cw, const float* __restrict__ cb,
    const float* __restrict__ dtb, const float* __restrict__ alog) {
  const int bid = blockIdx.x, tid = threadIdx.x;
  if (bid < CONV_BLKS) {
    const int ch  = (bid % 9) * 128 + tid;
    const int grp = bid / 9;
    const size_t pos0 = (size_t)grp * 8;
    const int l0 = (int)(pos0 & (SEQLEN - 1));
    const float* src = g_zx + pos0 * DPROJ + DINNER + ch;
    const float w0 = cw[ch * 4 + 0], w1 = cw[ch * 4 + 1];
    const float w2 = cw[ch * 4 + 2], w3 = cw[ch * 4 + 3];
    const float bias = cb[ch];
    float v[11];
    #pragma unroll
    for (int j = 0; j < 3; j++)
      v[j] = (l0 >= 3 - j) ? src[(ptrdiff_t)(j - 3) * DPROJ] : 0.f;
    #pragma unroll
    for (int j = 0; j < 8; j++)
      v[3 + j] = src[(ptrdiff_t)j * DPROJ];
    __half* dst = g_xbc + pos0 * CONVDIM + ch;
    #pragma unroll
    for (int j = 0; j < 8; j++) {
      float a = bias + w0 * v[j] + w1 * v[j + 1] + w2 * v[j + 2] + w3 * v[j + 3];
      dst[(size_t)j * CONVDIM] = __float2half(a / (1.f + __expf(-a)));
    }
    return;
  }
  const int gw = ((bid - CONV_BLKS) * 128 + tid) >> 5;
  const int lane = tid & 31;
  const int c = gw & (NC - 1);
  const int bh = gw >> 6;
  const int b = bh >> 4, h = bh & (NH - 1);
  const int t0 = c * CS;
  const int pos0 = b * SEQLEN + t0 + lane;
  const float bsh = dtb[h];
  const float A = -expf(alog[h]);
  float v0 = g_zx[(size_t)pos0 * DPROJ + DINNER + CONVDIM + h] + bsh;
  float v1 = g_zx[(size_t)(pos0 + 32) * DPROJ + DINNER + CONVDIM + h] + bsh;
  float sp0 = (v0 > 20.f) ? v0 : log1pf(expf(v0));
  float sp1 = (v1 > 20.f) ? v1 : log1pf(expf(v1));
  g_dt[pos0 * NH + h] = sp0;
  g_dt[(pos0 + 32) * NH + h] = sp1;
  float x0 = A * sp0, x1 = A * sp1;
  #pragma unroll
  for (int o = 1; o < 32; o <<= 1) {
    float t = __shfl_up_sync(0xFFFFFFFFu, x0, o);
    if (lane >= o) x0 += t;
  }
  float tot0 = __shfl_sync(0xFFFFFFFFu, x0, 31);
  #pragma unroll
  for (int o = 1; o < 32; o <<= 1) {
    float t = __shfl_up_sync(0xFFFFFFFFu, x1, o);
    if (lane >= o) x1 += t;
  }
  x1 += tot0;
  g_cl[bh * SEQLEN + t0 + lane] = x0;
  g_cl[bh * SEQLEN + t0 + 32 + lane] = x1;
}

// ---------------- intra-chunk SSD kernel (HMMA, vectorized smem ops) ---------
#define CLDH 72
#define CLDB 144
#define CH_SMEM (5 * 9216 + 128 * 4)

__global__ __launch_bounds__(256) void chunk_kernel(const float* __restrict__ Dv) {
  extern __shared__ __align__(16) __half sh[];
  __half* sC  = sh;            // [64][72] C[t][n]
  __half* sB  = sh + 4608;     // [64][72] B[s][n]
  __half* sX  = sh + 9216;     // [64][72] X[s][p]
  __half* sM  = sh + 13824;    // [64][72] M[t][s]
  __half* sXW = sh + 18432;    // [64][72] XW[s][p]
  float* scl = (float*)(sh + 23040);
  float* sdt = scl + 64;

  const int bid = blockIdx.x;
  const int c = bid & (NC - 1);
  const int bh = bid >> 6;
  const int h = bh & (NH - 1);
  const int b = bh >> 4;
  const int tid = threadIdx.x;
  const int t0 = c * CS;
  const int wid = tid >> 5, lane = tid & 31;

  {
    const int row = tid >> 2, cs = (tid & 3) * 16;
    const __half* base = g_xbc + (size_t)(b * SEQLEN + t0 + row) * CONVDIM;
    #pragma unroll
    for (int q = 0; q < 2; q++) {
      const int col = cs + q * 8;
      *(uint4*)(sB + row * CLDH + col) = *(const uint4*)(base + DINNER + col);
      *(uint4*)(sC + row * CLDH + col) = *(const uint4*)(base + DINNER + DSTATE + col);
      *(uint4*)(sX + row * CLDH + col) = *(const uint4*)(base + h * HD + col);
    }
    if (tid < 64) {
      scl[tid] = g_cl[bh * SEQLEN + t0 + tid];
      sdt[tid] = g_dt[(b * SEQLEN + t0 + tid) * NH + h];
    }
  }
  __syncthreads();

  const uint32_t uC = smem_u32(sC), uB = smem_u32(sB), uX = smem_u32(sX);
  const uint32_t uM = smem_u32(sM), uXW = smem_u32(sXW);
  const int mt0 = (wid & 3) * 16;
  const int nt0 = (wid >> 2) * 32;
  const int aoff = (lane & 15) * CLDB + (lane >> 4) * 16;
  const int boff = ((lane & 7) + ((lane >> 4) & 1) * 8) * CLDB + ((lane >> 3) & 1) * 16;
  const int bofft_row = (lane & 7) + ((lane >> 3) & 1) * 8;
  const int bofft_b   = ((lane >> 4) & 1) * 16;
  const int aofft_row = (lane & 7) + ((lane >> 4) & 1) * 8;
  const int aofft_b   = ((lane >> 3) & 1) * 16;
  const int rb = mt0 + (lane >> 2);
  const int cb = nt0 + (lane & 3) * 2;

  float acc[4][4];

  // ---- GEMM1: M0 = C @ B^T ----
  #pragma unroll
  for (int nt = 0; nt < 4; nt++)
    #pragma unroll
    for (int v = 0; v < 4; v++) acc[nt][v] = 0.f;
  #pragma unroll
  for (int ks = 0; ks < 4; ks++) {
    uint32_t af[4];
    ldm4(af, uC + (uint32_t)(mt0 * CLDB + aoff + ks * 32));
    #pragma unroll
    for (int p = 0; p < 2; p++) {
      uint32_t bf[4];
      ldm4(bf, uB + (uint32_t)((nt0 + p * 16) * CLDB + boff + ks * 32));
      mma16816(acc[2 * p],     af, &bf[0]);
      mma16816(acc[2 * p + 1], af, &bf[2]);
    }
  }
  // masked decay -> sM, packed half2 stores (rows rb and rb+8)
  {
    const float et1 = scl[rb], et2 = scl[rb + 8];
    const float dt1v = sdt[rb];   (void)dt1v;
    #pragma unroll
    for (int nt = 0; nt < 4; nt++) {
      const int s0 = cb + nt * 8;
      const float d0 = sdt[s0], d1 = sdt[s0 + 1];
      const float l0 = scl[s0], l1 = scl[s0 + 1];
      float v0 = (s0     <= rb) ? acc[nt][0] * __expf(et1 - l0) * d0 : 0.f;
      float v1 = (s0 + 1 <= rb) ? acc[nt][1] * __expf(et1 - l1) * d1 : 0.f;
      *(__half2*)(sM + rb * CLDH + s0) = __floats2half2_rn(v0, v1);
      float v2 = (s0     <= rb + 8) ? acc[nt][2] * __expf(et2 - l0) * d0 : 0.f;
      float v3 = (s0 + 1 <= rb + 8) ? acc[nt][3] * __expf(et2 - l1) * d1 : 0.f;
      *(__half2*)(sM + (rb + 8) * CLDH + s0) = __floats2half2_rn(v2, v3);
    }
  }
  // XW[s][p] = w[s] * X[s][p] -- vectorized uint4 load/store, fp32 math
  {
    const float Ltot = scl[63];
    const int row = tid >> 2, cs = (tid & 3) * 16;
    const float w = __expf(Ltot - scl[row]) * sdt[row];
    #pragma unroll
    for (int q = 0; q < 2; q++) {
      uint4 v = *(uint4*)(sX + row * CLDH + cs + q * 8);
      __half* hv = (__half*)&v;
      #pragma unroll
      for (int j = 0; j < 8; j++)
        hv[j] = __float2half(__half2float(hv[j]) * w);
      *(uint4*)(sXW + row * CLDH + cs + q * 8) = v;
    }
  }
  __syncthreads();

  // ---- GEMM2: Y = M @ X ----
  #pragma unroll
  for (int nt = 0; nt < 4; nt++)
    #pragma unroll
    for (int v = 0; v < 4; v++) acc[nt][v] = 0.f;
  #pragma unroll
  for (int ks = 0; ks < 4; ks++) {
    uint32_t af[4];
    ldm4(af, uM + (uint32_t)(mt0 * CLDB + aoff + ks * 32));
    #pragma unroll
    for (int p = 0; p < 2; p++) {
      uint32_t bf[4];
      ldm4t(bf, uX + (uint32_t)((ks * 16 + bofft_row) * CLDB
                                + (nt0 + p * 16) * 2 + bofft_b));
      mma16816(acc[2 * p],     af, &bf[0]);
      mma16816(acc[2 * p + 1], af, &bf[2]);
    }
  }
  {
    const float Dh = Dv[h];
    #pragma unroll
    for (int nt = 0; nt < 4; nt++) {
      const int p = cb + nt * 8;
      const int t1 = rb, t2 = rb + 8;
      float2 x1 = __half22float2(*(__half2*)(sX + t1 * CLDH + p));
      float2 x2 = __half22float2(*(__half2*)(sX + t2 * CLDH + p));
      float2 o01 = make_float2(acc[nt][0] + Dh * x1.x, acc[nt][1] + Dh * x1.y);
      float2 o23 = make_float2(acc[nt][2] + Dh * x2.x, acc[nt][3] + Dh * x2.y);
      *(float2*)&g_y[(size_t)(b * SEQLEN + t0 + t1) * DINNER + h * HD + p] = o01;
      *(float2*)&g_y[(size_t)(b * SEQLEN + t0 + t2) * DINNER + h * HD + p] = o23;
    }
  }

  // ---- GEMM3: S = XW^T @ B ----
  #pragma unroll
  for (int nt = 0; nt < 4; nt++)
    #pragma unroll
    for (int v = 0; v < 4; v++) acc[nt][v] = 0.f;
  #pragma unroll
  for (int ks = 0; ks < 4; ks++) {
    uint32_t af[4];
    ldm4t(af, uXW + (uint32_t)((ks * 16 + aofft_row) * CLDB + mt0 * 2 + aofft_b));
    #pragma unroll
    for (int p = 0; p < 2; p++) {
      uint32_t bf[4];
      ldm4t(bf, uB + (uint32_t)((ks * 16 + bofft_row) * CLDB
                                + (nt0 + p * 16) * 2 + bofft_b));
      mma16816(acc[2 * p],     af, &bf[0]);
      mma16816(acc[2 * p + 1], af, &bf[2]);
    }
  }
  #pragma unroll
  for (int nt = 0; nt < 4; nt++) {
    const int n = cb + nt * 8;
    *(float2*)&g_S[(size_t)bid * 4096 + rb * 64 + n] =
        make_float2(acc[nt][0], acc[nt][1]);
    *(float2*)&g_S[(size_t)bid * 4096 + (rb + 8) * 64 + n] =
        make_float2(acc[nt][2], acc[nt][3]);
  }
}

// ---------------- inter-chunk state scan (fp32 in, fp16 prefix out) ---------
__global__ __launch_bounds__(128) void scan_kernel() {
  const int bh = blockIdx.x;
  const int slice = blockIdx.y;
  const int tid = threadIdx.x;
  const int off = slice * 512 + tid * 4;
  float run[4] = {0.f, 0.f, 0.f, 0.f};
  for (int c = 0; c < NC; c++) {
    float a = __expf(g_cl[bh * SEQLEN + c * CS + CS - 1]);
    const float* p = g_S + (size_t)(bh * NC + c) * 4096 + off;
    float4 v = *(const float4*)p;
    __half2* d = (__half2*)(g_Sh + (size_t)(bh * NC + c) * 4096 + off);
    d[0] = __floats2half2_rn(run[0], run[1]);
    d[1] = __floats2half2_rn(run[2], run[3]);
    run[0] = a * run[0] + v.x;
    run[1] = a * run[1] + v.y;
    run[2] = a * run[2] + v.z;
    run[3] = a * run[3] + v.w;
  }
}

// ---------------- inter-chunk contribution (HMMA fp16) ----------------------
__global__ __launch_bounds__(256) void inter_kernel() {
  __shared__ __align__(16) __half sC[4608];
  __shared__ __align__(16) __half sS[4608];
  __shared__ float scl[64];
  const int bid = blockIdx.x;
  const int c = bid & (NC - 1);
  const int bh = bid >> 6;
  const int h = bh & (NH - 1);
  const int b = bh >> 4;
  const int tid = threadIdx.x;
  const int t0 = c * CS;
  const int wid = tid >> 5, lane = tid & 31;

  {
    const int row = tid >> 2, cs = (tid & 3) * 16;
    const __half* cbase = g_xbc + (size_t)(b * SEQLEN + t0 + row) * CONVDIM
                          + DINNER + DSTATE;
    #pragma unroll
    for (int q = 0; q < 2; q++) {
      *(uint4*)(sC + row * CLDH + cs + q * 8) = *(const uint4*)(cbase + cs + q * 8);
      *(uint4*)(sS + row * CLDH + cs + q * 8) =
          *(const uint4*)(g_Sh + (size_t)bid * 4096 + row * 64 + cs + q * 8);
    }
    if (tid < 64) scl[tid] = g_cl[bh * SEQLEN + t0 + tid];
  }
  __syncthreads();

  const uint32_t uC = smem_u32(sC), uS = smem_u32(sS);
  const int mt0 = (wid & 3) * 16;
  const int nt0 = (wid >> 2) * 32;
  const int aoff = (lane & 15) * CLDB + (lane >> 4) * 16;
  const int boff = ((lane & 7) + ((lane >> 4) & 1) * 8) * CLDB + ((lane >> 3) & 1) * 16;
  const int rb = mt0 + (lane >> 2);
  const int cb = nt0 + (lane & 3) * 2;

  float acc[4][4];
  #pragma unroll
  for (int nt = 0; nt < 4; nt++)
    #pragma unroll
    for (int v = 0; v < 4; v++) acc[nt][v] = 0.f;
  #pragma unroll
  for (int ks = 0; ks < 4; ks++) {
    uint32_t af[4];
    ldm4(af, uC + (uint32_t)(mt0 * CLDB + aoff + ks * 32));
    #pragma unroll
    for (int p = 0; p < 2; p++) {
      uint32_t bf[4];
      ldm4(bf, uS + (uint32_t)((nt0 + p * 16) * CLDB + boff + ks * 32));
      mma16816(acc[2 * p],     af, &bf[0]);
      mma16816(acc[2 * p + 1], af, &bf[2]);
    }
  }
  const float e1 = __expf(scl[rb]);
  const float e2 = __expf(scl[rb + 8]);
  #pragma unroll
  for (int nt = 0; nt < 4; nt++) {
    const int p = cb + nt * 8;
    size_t o1 = (size_t)(b * SEQLEN + t0 + rb) * DINNER + h * HD + p;
    size_t o2 = (size_t)(b * SEQLEN + t0 + rb + 8) * DINNER + h * HD + p;
    float2 c1 = *(float2*)&g_y[o1];
    float2 c2 = *(float2*)&g_y[o2];
    c1.x += e1 * acc[nt][0]; c1.y += e1 * acc[nt][1];
    c2.x += e2 * acc[nt][2]; c2.y += e2 * acc[nt][3];
    *(float2*)&g_y[o1] = c1;
    *(float2*)&g_y[o2] = c2;
  }
}

// ---------------- gate + RMSNorm, emits fp16 ---------------------------------
__global__ __launch_bounds__(256) void norm_kernel(const float* __restrict__ nw) {
  const int pos = blockIdx.x, tid = threadIdx.x;
  float4 yv = *(const float4*)(g_y  + (size_t)pos * DINNER + tid * 4);
  float4 zv = *(const float4*)(g_zx + (size_t)pos * DPROJ  + tid * 4);
  float4 g;
  g.x = yv.x * (zv.x / (1.f + __expf(-zv.x)));
  g.y = yv.y * (zv.y / (1.f + __expf(-zv.y)));
  g.z = yv.z * (zv.z / (1.f + __expf(-zv.z)));
  g.w = yv.w * (zv.w / (1.f + __expf(-zv.w)));
  float ssq = g.x * g.x + g.y * g.y + g.z * g.z + g.w * g.w;
  #pragma unroll
  for (int o = 16; o; o >>= 1) ssq += __shfl_xor_sync(0xFFFFFFFFu, ssq, o);
  __shared__ float red[8];
  if ((tid & 31) == 0) red[tid >> 5] = ssq;
  __syncthreads();
  float tot = red[0] + red[1] + red[2] + red[3] + red[4] + red[5] + red[6] + red[7];
  float scale = rsqrtf(tot * (1.f / DINNER) + EPSV);
  float4 w = *(const float4*)(nw + tid * 4);
  __half2* dst = (__half2*)(g_yh + (size_t)pos * DINNER + tid * 4);
  dst[0] = __floats2half2_rn(g.x * scale * w.x, g.y * scale * w.y);
  dst[1] = __floats2half2_rn(g.z * scale * w.z, g.w * scale * w.w);
}

// ---------------- launch ------------------------------------------------------
extern "C" void kernel_launch(void* const* d_in, const int* in_sizes, int n_in,
                              void* d_out, int out_size) {
  const float* x       = (const float*)d_in[0];
  const float* W_in    = (const float*)d_in[1];
  const float* conv_w  = (const float*)d_in[2];
  const float* conv_b  = (const float*)d_in[3];
  const float* dt_bias = (const float*)d_in[4];
  const float* A_log   = (const float*)d_in[5];
  const float* Dv      = (const float*)d_in[6];
  const float* nw      = (const float*)d_in[7];
  const float* W_out   = (const float*)d_in[8];
  float* out = (float*)d_out;

  void* p;
  cudaGetSymbolAddress(&p, g_zx);  float* zx = (float*)p;
  cudaGetSymbolAddress(&p, g_xh);  __half* xh  = (__half*)p;
  cudaGetSymbolAddress(&p, g_w1h); __half* w1h = (__half*)p;
  cudaGetSymbolAddress(&p, g_yh);  __half* yh  = (__half*)p;
  cudaGetSymbolAddress(&p, g_w2h); __half* w2h = (__half*)p;

  cudaFuncSetAttribute(chunk_kernel, cudaFuncAttributeMaxDynamicSharedMemorySize, CH_SMEM);
  cudaFuncSetAttribute(gemm_tc, cudaFuncAttributeMaxDynamicSharedMemorySize, SM_TOTAL);

  dim3 blk(256);
  // 0) fused prep
  prep_kernel<<<PREP_A + PREP_B + PREP_C, blk>>>(x, W_in, W_out);
  // 1) in-projection
  gemm_tc<<<dim3(NPAD1 / 128, NPOS / 128), dim3(128), SM_TOTAL>>>(xh, w1h, zx,
                                                                  DMODEL, DPROJ, DPROJ);
  // 2) fused conv+silu and dt+cumlog
  convdt_kernel<<<CONV_BLKS + 512, dim3(128)>>>(conv_w, conv_b, dt_bias, A_log);
  // 3) intra-chunk SSD
  chunk_kernel<<<BATCH * NH * NC, blk, CH_SMEM>>>(Dv);
  // 4) inter-chunk state scan
  scan_kernel<<<dim3(BATCH * NH, 8), dim3(128)>>>();
  // 5) inter-chunk correction
  inter_kernel<<<BATCH * NH * NC, blk>>>();
  // 6) gate + RMSNorm
  norm_kernel<<<NPOS, blk>>>(nw);
  // 7) out-projection
  gemm_tc<<<dim3(DMODEL / 128, NPOS / 128), dim3(128), SM_TOTAL>>>(yh, w2h, out,
                                                                   DINNER, DMODEL, DMODEL);
}

// round 16
// speedup vs baseline: 1.0838x; 1.0480x over previous
#include <cuda_runtime.h>
#include <cuda_fp16.h>
#include <cstdint>
#include <cstddef>

#define BATCH   2
#define SEQLEN  4096
#define DMODEL  512
#define DINNER  1024
#define NH      16
#define HD      64
#define DSTATE  64
#define CONVDIM 1152
#define DPROJ   2192
#define NPOS    (BATCH * SEQLEN)   // 8192
#define NC      64
#define CS      64
#define EPSV    1e-5f
#define NPAD1   2304

// ---------------- scratch (static device globals) ---------------------------
__device__ float  g_zx [(size_t)NPOS * DPROJ];
__device__ __half g_xbc[(size_t)NPOS * CONVDIM];
__device__ float  g_dt [NPOS * NH];
__device__ float  g_cl [BATCH * NH * SEQLEN];
__device__ __half g_S  [(size_t)BATCH * NH * NC * HD * DSTATE];   // fp16 chunk states
__device__ __half g_Sh [(size_t)BATCH * NH * NC * HD * DSTATE];   // fp16 prefix states
__device__ float  g_y  [(size_t)NPOS * DINNER];

__device__ __half g_xh [(size_t)NPOS * DMODEL];
__device__ __half g_w1h[(size_t)NPAD1 * DMODEL];
__device__ __half g_yh [(size_t)NPOS * DINNER];
__device__ __half g_w2h[(size_t)DMODEL * DINNER];

// ---------------- PTX helpers ------------------------------------------------
__device__ __forceinline__ uint32_t smem_u32(const void* p) {
  uint32_t a;
  asm("{ .reg .u64 t; cvta.to.shared.u64 t, %1; cvt.u32.u64 %0, t; }" : "=r"(a) : "l"(p));
  return a;
}
__device__ __forceinline__ void ldm4(uint32_t* r, uint32_t addr) {
  asm volatile("ldmatrix.sync.aligned.m8n8.x4.shared.b16 {%0,%1,%2,%3}, [%4];"
               : "=r"(r[0]), "=r"(r[1]), "=r"(r[2]), "=r"(r[3]) : "r"(addr));
}
__device__ __forceinline__ void ldm4t(uint32_t* r, uint32_t addr) {
  asm volatile("ldmatrix.sync.aligned.m8n8.x4.trans.shared.b16 {%0,%1,%2,%3}, [%4];"
               : "=r"(r[0]), "=r"(r[1]), "=r"(r[2]), "=r"(r[3]) : "r"(addr));
}
__device__ __forceinline__ void mma16816(float* c, const uint32_t* a, const uint32_t* b) {
  asm volatile(
      "mma.sync.aligned.m16n8k16.row.col.f32.f16.f16.f32 "
      "{%0,%1,%2,%3}, {%4,%5,%6,%7}, {%8,%9}, {%0,%1,%2,%3};"
      : "+f"(c[0]), "+f"(c[1]), "+f"(c[2]), "+f"(c[3])
      : "r"(a[0]), "r"(a[1]), "r"(a[2]), "r"(a[3]), "r"(b[0]), "r"(b[1]));
}
#define CPASYNC(dst, src) \
  asm volatile("cp.async.cg.shared.global [%0], [%1], 16;" :: "r"(dst), "l"(src))
#define CPCOMMIT() asm volatile("cp.async.commit_group;" ::: "memory")
#define CPWAIT(n)  asm volatile("cp.async.wait_group %0;" :: "n"(n) : "memory")
#define SWZ(off)   ((off) ^ (((off) >> 3) & 0x70))

// ---------------- HMMA GEMM (fp16): C = A @ B^T ------------------------------
#define SM_BUF   32768
#define SM_TOTAL (3 * SM_BUF)

__global__ __launch_bounds__(128, 2) void gemm_tc(
    const __half* __restrict__ A, const __half* __restrict__ B,
    float* __restrict__ C, int K, int N, int ldc) {
  extern __shared__ char smem[];
  const uint32_t sb = smem_u32(smem);
  const int tid = threadIdx.x, wid = tid >> 5, lane = tid & 31;
  const int bm = blockIdx.y * 128, bn = blockIdx.x * 128;
  const int wrow = wid & 1, wcol = wid >> 1;

  float acc[4][8][4];
  #pragma unroll
  for (int i = 0; i < 4; i++)
    #pragma unroll
    for (int j = 0; j < 8; j++)
      #pragma unroll
      for (int v = 0; v < 4; v++) acc[i][j][v] = 0.f;

  const int nK = K >> 6;

  #pragma unroll
  for (int pre = 0; pre < 2; pre++) {
    if (pre < nK) {
      const int k0 = pre << 6;
      const uint32_t bbuf = sb + pre * SM_BUF;
      #pragma unroll
      for (int it = 0; it < 16; it++) {
        const int u = it * 128 + tid;
        const int tile = u >> 10, idx = u & 1023;
        const int row = idx >> 3, c16 = idx & 7;
        const uint32_t dst = bbuf + tile * 16384 + SWZ((uint32_t)(row * 128 + c16 * 16));
        const __half* src = (tile == 0) ? A + (size_t)(bm + row) * K + k0 + c16 * 8
                                        : B + (size_t)(bn + row) * K + k0 + c16 * 8;
        CPASYNC(dst, src);
      }
    }
    CPCOMMIT();
  }

  int buf = 0;
  for (int i = 0; i < nK; i++) {
    if (i + 2 < nK) {
      const int k0 = (i + 2) << 6;
      const uint32_t bbuf = sb + ((buf + 2 >= 3) ? buf - 1 : buf + 2) * SM_BUF;
      #pragma unroll
      for (int it = 0; it < 16; it++) {
        const int u = it * 128 + tid;
        const int tile = u >> 10, idx = u & 1023;
        const int row = idx >> 3, c16 = idx & 7;
        const uint32_t dst = bbuf + tile * 16384 + SWZ((uint32_t)(row * 128 + c16 * 16));
        const __half* src = (tile == 0) ? A + (size_t)(bm + row) * K + k0 + c16 * 8
                                        : B + (size_t)(bn + row) * K + k0 + c16 * 8;
        CPASYNC(dst, src);
      }
    }
    CPCOMMIT();
    CPWAIT(2);
    __syncthreads();

    const uint32_t tb = sb + buf * SM_BUF;
    const int arow = wrow * 64 + (lane & 15);
    const int brow = wcol * 64 + (lane & 7) + ((lane >> 4) & 1) * 8;
    const int akb  = (lane >> 4) * 16;
    const int bkb  = ((lane >> 3) & 1) * 16;

    #pragma unroll
    for (int ks = 0; ks < 4; ks++) {
      uint32_t ah[4][4];
      #pragma unroll
      for (int mt = 0; mt < 4; mt++) {
        const uint32_t off = SWZ((uint32_t)((arow + mt * 16) * 128 + ks * 32 + akb));
        ldm4(ah[mt], tb + off);
      }
      #pragma unroll
      for (int p = 0; p < 4; p++) {
        uint32_t bf[4];
        const uint32_t off = SWZ((uint32_t)((brow + p * 16) * 128 + ks * 32 + bkb));
        ldm4(bf, tb + 16384 + off);
        #pragma unroll
        for (int mt = 0; mt < 4; mt++) {
          mma16816(acc[mt][2 * p],     ah[mt], &bf[0]);
          mma16816(acc[mt][2 * p + 1], ah[mt], &bf[2]);
        }
      }
    }
    __syncthreads();
    buf = (buf + 1 >= 3) ? 0 : buf + 1;
  }

  const int r0 = bm + wrow * 64 + (lane >> 2);
  const int c0 = bn + wcol * 64 + (lane & 3) * 2;
  #pragma unroll
  for (int mt = 0; mt < 4; mt++)
    #pragma unroll
    for (int nt = 0; nt < 8; nt++) {
      const int col = c0 + nt * 8;
      if (col < N) {
        const int row = r0 + mt * 16;
        *(float2*)&C[(size_t)row * ldc + col] =
            make_float2(acc[mt][nt][0], acc[mt][nt][1]);
        *(float2*)&C[(size_t)(row + 8) * ldc + col] =
            make_float2(acc[mt][nt][2], acc[mt][nt][3]);
      }
    }
}

// ---------------- fused prep: x->fp16 cast + both W transposes ---------------
#define PREP_A 16384
#define PREP_B 1152
#define PREP_C 512

__global__ __launch_bounds__(256) void prep_kernel(
    const float* __restrict__ x, const float* __restrict__ W_in,
    const float* __restrict__ W_out) {
  __shared__ float t[32][33];
  const int bid = blockIdx.x, tid = threadIdx.x;
  if (bid < PREP_A) {
    const int i = bid * 256 + tid;
    g_xh[i] = __float2half(x[i]);
    return;
  }
  const float* W;
  __half* th;
  int K, N, bx, by;
  if (bid < PREP_A + PREP_B) {
    const int lb = bid - PREP_A;
    W = W_in; th = g_w1h; K = DMODEL; N = DPROJ;
    bx = lb % (NPAD1 / 32); by = lb / (NPAD1 / 32);
  } else {
    const int lb = bid - PREP_A - PREP_B;
    W = W_out; th = g_w2h; K = DINNER; N = DMODEL;
    bx = lb % (DMODEL / 32); by = lb / (DMODEL / 32);
  }
  const int n0 = bx * 32, k0 = by * 32;
  const int tx = tid & 31, ty = tid >> 5;
  #pragma unroll
  for (int r = 0; r < 4; r++) {
    int k = k0 + ty + r * 8, n = n0 + tx;
    t[ty + r * 8][tx] = (n < N) ? W[(size_t)k * N + n] : 0.f;
  }
  __syncthreads();
  #pragma unroll
  for (int r = 0; r < 4; r++) {
    int n = n0 + ty + r * 8, k = k0 + tx;
    th[(size_t)n * K + k] = __float2half(t[tx][ty + r * 8]);
  }
}

// ---------------- fused conv+silu and dt+cumlog ------------------------------
#define CONV_BLKS 9216

__global__ __launch_bounds__(128) void convdt_kernel(
    const float* __restrict__ cw, const float* __restrict__ cb,
    const float* __restrict__ dtb, const float* __restrict__ alog) {
  const int bid = blockIdx.x, tid = threadIdx.x;
  if (bid < CONV_BLKS) {
    const int ch  = (bid % 9) * 128 + tid;
    const int grp = bid / 9;
    const size_t pos0 = (size_t)grp * 8;
    const int l0 = (int)(pos0 & (SEQLEN - 1));
    const float* src = g_zx + pos0 * DPROJ + DINNER + ch;
    const float w0 = cw[ch * 4 + 0], w1 = cw[ch * 4 + 1];
    const float w2 = cw[ch * 4 + 2], w3 = cw[ch * 4 + 3];
    const float bias = cb[ch];
    float v[11];
    #pragma unroll
    for (int j = 0; j < 3; j++)
      v[j] = (l0 >= 3 - j) ? src[(ptrdiff_t)(j - 3) * DPROJ] : 0.f;
    #pragma unroll
    for (int j = 0; j < 8; j++)
      v[3 + j] = src[(ptrdiff_t)j * DPROJ];
    __half* dst = g_xbc + pos0 * CONVDIM + ch;
    #pragma unroll
    for (int j = 0; j < 8; j++) {
      float a = bias + w0 * v[j] + w1 * v[j + 1] + w2 * v[j + 2] + w3 * v[j + 3];
      dst[(size_t)j * CONVDIM] = __float2half(a / (1.f + __expf(-a)));
    }
    return;
  }
  const int gw = ((bid - CONV_BLKS) * 128 + tid) >> 5;
  const int lane = tid & 31;
  const int c = gw & (NC - 1);
  const int bh = gw >> 6;
  const int b = bh >> 4, h = bh & (NH - 1);
  const int t0 = c * CS;
  const int pos0 = b * SEQLEN + t0 + lane;
  const float bsh = dtb[h];
  const float A = -expf(alog[h]);
  float v0 = g_zx[(size_t)pos0 * DPROJ + DINNER + CONVDIM + h] + bsh;
  float v1 = g_zx[(size_t)(pos0 + 32) * DPROJ + DINNER + CONVDIM + h] + bsh;
  float sp0 = (v0 > 20.f) ? v0 : log1pf(expf(v0));
  float sp1 = (v1 > 20.f) ? v1 : log1pf(expf(v1));
  g_dt[pos0 * NH + h] = sp0;
  g_dt[(pos0 + 32) * NH + h] = sp1;
  float x0 = A * sp0, x1 = A * sp1;
  #pragma unroll
  for (int o = 1; o < 32; o <<= 1) {
    float t = __shfl_up_sync(0xFFFFFFFFu, x0, o);
    if (lane >= o) x0 += t;
  }
  float tot0 = __shfl_sync(0xFFFFFFFFu, x0, 31);
  #pragma unroll
  for (int o = 1; o < 32; o <<= 1) {
    float t = __shfl_up_sync(0xFFFFFFFFu, x1, o);
    if (lane >= o) x1 += t;
  }
  x1 += tot0;
  g_cl[bh * SEQLEN + t0 + lane] = x0;
  g_cl[bh * SEQLEN + t0 + 32 + lane] = x1;
}

// ---------------- intra-chunk SSD kernel (HMMA, vectorized smem ops) ---------
#define CLDH 72
#define CLDB 144
#define CH_SMEM (5 * 9216 + 128 * 4)

__global__ __launch_bounds__(256) void chunk_kernel(const float* __restrict__ Dv) {
  extern __shared__ __align__(16) __half sh[];
  __half* sC  = sh;            // [64][72] C[t][n]
  __half* sB  = sh + 4608;     // [64][72] B[s][n]
  __half* sX  = sh + 9216;     // [64][72] X[s][p]
  __half* sM  = sh + 13824;    // [64][72] M[t][s]
  __half* sXW = sh + 18432;    // [64][72] XW[s][p]
  float* scl = (float*)(sh + 23040);
  float* sdt = scl + 64;

  const int bid = blockIdx.x;
  const int c = bid & (NC - 1);
  const int bh = bid >> 6;
  const int h = bh & (NH - 1);
  const int b = bh >> 4;
  const int tid = threadIdx.x;
  const int t0 = c * CS;
  const int wid = tid >> 5, lane = tid & 31;

  {
    const int row = tid >> 2, cs = (tid & 3) * 16;
    const __half* base = g_xbc + (size_t)(b * SEQLEN + t0 + row) * CONVDIM;
    #pragma unroll
    for (int q = 0; q < 2; q++) {
      const int col = cs + q * 8;
      *(uint4*)(sB + row * CLDH + col) = *(const uint4*)(base + DINNER + col);
      *(uint4*)(sC + row * CLDH + col) = *(const uint4*)(base + DINNER + DSTATE + col);
      *(uint4*)(sX + row * CLDH + col) = *(const uint4*)(base + h * HD + col);
    }
    if (tid < 64) {
      scl[tid] = g_cl[bh * SEQLEN + t0 + tid];
      sdt[tid] = g_dt[(b * SEQLEN + t0 + tid) * NH + h];
    }
  }
  __syncthreads();

  const uint32_t uC = smem_u32(sC), uB = smem_u32(sB), uX = smem_u32(sX);
  const uint32_t uM = smem_u32(sM), uXW = smem_u32(sXW);
  const int mt0 = (wid & 3) * 16;
  const int nt0 = (wid >> 2) * 32;
  const int aoff = (lane & 15) * CLDB + (lane >> 4) * 16;
  const int boff = ((lane & 7) + ((lane >> 4) & 1) * 8) * CLDB + ((lane >> 3) & 1) * 16;
  const int bofft_row = (lane & 7) + ((lane >> 3) & 1) * 8;
  const int bofft_b   = ((lane >> 4) & 1) * 16;
  const int aofft_row = (lane & 7) + ((lane >> 4) & 1) * 8;
  const int aofft_b   = ((lane >> 3) & 1) * 16;
  const int rb = mt0 + (lane >> 2);
  const int cb = nt0 + (lane & 3) * 2;

  float acc[4][4];

  // ---- GEMM1: M0 = C @ B^T ----
  #pragma unroll
  for (int nt = 0; nt < 4; nt++)
    #pragma unroll
    for (int v = 0; v < 4; v++) acc[nt][v] = 0.f;
  #pragma unroll
  for (int ks = 0; ks < 4; ks++) {
    uint32_t af[4];
    ldm4(af, uC + (uint32_t)(mt0 * CLDB + aoff + ks * 32));
    #pragma unroll
    for (int p = 0; p < 2; p++) {
      uint32_t bf[4];
      ldm4(bf, uB + (uint32_t)((nt0 + p * 16) * CLDB + boff + ks * 32));
      mma16816(acc[2 * p],     af, &bf[0]);
      mma16816(acc[2 * p + 1], af, &bf[2]);
    }
  }
  {
    const float et1 = scl[rb], et2 = scl[rb + 8];
    #pragma unroll
    for (int nt = 0; nt < 4; nt++) {
      const int s0 = cb + nt * 8;
      const float d0 = sdt[s0], d1 = sdt[s0 + 1];
      const float l0 = scl[s0], l1 = scl[s0 + 1];
      float v0 = (s0     <= rb) ? acc[nt][0] * __expf(et1 - l0) * d0 : 0.f;
      float v1 = (s0 + 1 <= rb) ? acc[nt][1] * __expf(et1 - l1) * d1 : 0.f;
      *(__half2*)(sM + rb * CLDH + s0) = __floats2half2_rn(v0, v1);
      float v2 = (s0     <= rb + 8) ? acc[nt][2] * __expf(et2 - l0) * d0 : 0.f;
      float v3 = (s0 + 1 <= rb + 8) ? acc[nt][3] * __expf(et2 - l1) * d1 : 0.f;
      *(__half2*)(sM + (rb + 8) * CLDH + s0) = __floats2half2_rn(v2, v3);
    }
  }
  {
    const float Ltot = scl[63];
    const int row = tid >> 2, cs = (tid & 3) * 16;
    const float w = __expf(Ltot - scl[row]) * sdt[row];
    #pragma unroll
    for (int q = 0; q < 2; q++) {
      uint4 v = *(uint4*)(sX + row * CLDH + cs + q * 8);
      __half* hv = (__half*)&v;
      #pragma unroll
      for (int j = 0; j < 8; j++)
        hv[j] = __float2half(__half2float(hv[j]) * w);
      *(uint4*)(sXW + row * CLDH + cs + q * 8) = v;
    }
  }
  __syncthreads();

  // ---- GEMM2: Y = M @ X ----
  #pragma unroll
  for (int nt = 0; nt < 4; nt++)
    #pragma unroll
    for (int v = 0; v < 4; v++) acc[nt][v] = 0.f;
  #pragma unroll
  for (int ks = 0; ks < 4; ks++) {
    uint32_t af[4];
    ldm4(af, uM + (uint32_t)(mt0 * CLDB + aoff + ks * 32));
    #pragma unroll
    for (int p = 0; p < 2; p++) {
      uint32_t bf[4];
      ldm4t(bf, uX + (uint32_t)((ks * 16 + bofft_row) * CLDB
                                + (nt0 + p * 16) * 2 + bofft_b));
      mma16816(acc[2 * p],     af, &bf[0]);
      mma16816(acc[2 * p + 1], af, &bf[2]);
    }
  }
  {
    const float Dh = Dv[h];
    #pragma unroll
    for (int nt = 0; nt < 4; nt++) {
      const int p = cb + nt * 8;
      const int t1 = rb, t2 = rb + 8;
      float2 x1 = __half22float2(*(__half2*)(sX + t1 * CLDH + p));
      float2 x2 = __half22float2(*(__half2*)(sX + t2 * CLDH + p));
      float2 o01 = make_float2(acc[nt][0] + Dh * x1.x, acc[nt][1] + Dh * x1.y);
      float2 o23 = make_float2(acc[nt][2] + Dh * x2.x, acc[nt][3] + Dh * x2.y);
      *(float2*)&g_y[(size_t)(b * SEQLEN + t0 + t1) * DINNER + h * HD + p] = o01;
      *(float2*)&g_y[(size_t)(b * SEQLEN + t0 + t2) * DINNER + h * HD + p] = o23;
    }
  }

  // ---- GEMM3: S = XW^T @ B  (fp16 full-sector stores) ----
  #pragma unroll
  for (int nt = 0; nt < 4; nt++)
    #pragma unroll
    for (int v = 0; v < 4; v++) acc[nt][v] = 0.f;
  #pragma unroll
  for (int ks = 0; ks < 4; ks++) {
    uint32_t af[4];
    ldm4t(af, uXW + (uint32_t)((ks * 16 + aofft_row) * CLDB + mt0 * 2 + aofft_b));
    #pragma unroll
    for (int p = 0; p < 2; p++) {
      uint32_t bf[4];
      ldm4t(bf, uB + (uint32_t)((ks * 16 + bofft_row) * CLDB
                                + (nt0 + p * 16) * 2 + bofft_b));
      mma16816(acc[2 * p],     af, &bf[0]);
      mma16816(acc[2 * p + 1], af, &bf[2]);
    }
  }
  #pragma unroll
  for (int nt = 0; nt < 4; nt++) {
    const int n = cb + nt * 8;
    *(__half2*)&g_S[(size_t)bid * 4096 + rb * 64 + n] =
        __floats2half2_rn(acc[nt][0], acc[nt][1]);
    *(__half2*)&g_S[(size_t)bid * 4096 + (rb + 8) * 64 + n] =
        __floats2half2_rn(acc[nt][2], acc[nt][3]);
  }
}

// ---------------- inter-chunk state scan (fp16 in, fp16 prefix out) ---------
__global__ __launch_bounds__(128) void scan_kernel() {
  const int bh = blockIdx.x;
  const int slice = blockIdx.y;
  const int tid = threadIdx.x;
  const int off = slice * 512 + tid * 4;
  float run[4] = {0.f, 0.f, 0.f, 0.f};
  for (int c = 0; c < NC; c++) {
    float a = __expf(g_cl[bh * SEQLEN + c * CS + CS - 1]);
    const __half2* p = (const __half2*)(g_S + (size_t)(bh * NC + c) * 4096 + off);
    float2 v01 = __half22float2(p[0]);
    float2 v23 = __half22float2(p[1]);
    __half2* d = (__half2*)(g_Sh + (size_t)(bh * NC + c) * 4096 + off);
    d[0] = __floats2half2_rn(run[0], run[1]);
    d[1] = __floats2half2_rn(run[2], run[3]);
    run[0] = a * run[0] + v01.x;
    run[1] = a * run[1] + v01.y;
    run[2] = a * run[2] + v23.x;
    run[3] = a * run[3] + v23.y;
  }
}

// ---------------- inter-chunk contribution (HMMA fp16) ----------------------
__global__ __launch_bounds__(256) void inter_kernel() {
  __shared__ __align__(16) __half sC[4608];
  __shared__ __align__(16) __half sS[4608];
  __shared__ float scl[64];
  const int bid = blockIdx.x;
  const int c = bid & (NC - 1);
  const int bh = bid >> 6;
  const int h = bh & (NH - 1);
  const int b = bh >> 4;
  const int tid = threadIdx.x;
  const int t0 = c * CS;
  const int wid = tid >> 5, lane = tid & 31;

  {
    const int row = tid >> 2, cs = (tid & 3) * 16;
    const __half* cbase = g_xbc + (size_t)(b * SEQLEN + t0 + row) * CONVDIM
                          + DINNER + DSTATE;
    #pragma unroll
    for (int q = 0; q < 2; q++) {
      *(uint4*)(sC + row * CLDH + cs + q * 8) = *(const uint4*)(cbase + cs + q * 8);
      *(uint4*)(sS + row * CLDH + cs + q * 8) =
          *(const uint4*)(g_Sh + (size_t)bid * 4096 + row * 64 + cs + q * 8);
    }
    if (tid < 64) scl[tid] = g_cl[bh * SEQLEN + t0 + tid];
  }
  __syncthreads();

  const uint32_t uC = smem_u32(sC), uS = smem_u32(sS);
  const int mt0 = (wid & 3) * 16;
  const int nt0 = (wid >> 2) * 32;
  const int aoff = (lane & 15) * CLDB + (lane >> 4) * 16;
  const int boff = ((lane & 7) + ((lane >> 4) & 1) * 8) * CLDB + ((lane >> 3) & 1) * 16;
  const int rb = mt0 + (lane >> 2);
  const int cb = nt0 + (lane & 3) * 2;

  float acc[4][4];
  #pragma unroll
  for (int nt = 0; nt < 4; nt++)
    #pragma unroll
    for (int v = 0; v < 4; v++) acc[nt][v] = 0.f;
  #pragma unroll
  for (int ks = 0; ks < 4; ks++) {
    uint32_t af[4];
    ldm4(af, uC + (uint32_t)(mt0 * CLDB + aoff + ks * 32));
    #pragma unroll
    for (int p = 0; p < 2; p++) {
      uint32_t bf[4];
      ldm4(bf, uS + (uint32_t)((nt0 + p * 16) * CLDB + boff + ks * 32));
      mma16816(acc[2 * p],     af, &bf[0]);
      mma16816(acc[2 * p + 1], af, &bf[2]);
    }
  }
  const float e1 = __expf(scl[rb]);
  const float e2 = __expf(scl[rb + 8]);
  #pragma unroll
  for (int nt = 0; nt < 4; nt++) {
    const int p = cb + nt * 8;
    size_t o1 = (size_t)(b * SEQLEN + t0 + rb) * DINNER + h * HD + p;
    size_t o2 = (size_t)(b * SEQLEN + t0 + rb + 8) * DINNER + h * HD + p;
    float2 c1 = *(float2*)&g_y[o1];
    float2 c2 = *(float2*)&g_y[o2];
    c1.x += e1 * acc[nt][0]; c1.y += e1 * acc[nt][1];
    c2.x += e2 * acc[nt][2]; c2.y += e2 * acc[nt][3];
    *(float2*)&g_y[o1] = c1;
    *(float2*)&g_y[o2] = c2;
  }
}

// ---------------- gate + RMSNorm, emits fp16 ---------------------------------
__global__ __launch_bounds__(256) void norm_kernel(const float* __restrict__ nw) {
  const int pos = blockIdx.x, tid = threadIdx.x;
  float4 yv = *(const float4*)(g_y  + (size_t)pos * DINNER + tid * 4);
  float4 zv = *(const float4*)(g_zx + (size_t)pos * DPROJ  + tid * 4);
  float4 g;
  g.x = yv.x * (zv.x / (1.f + __expf(-zv.x)));
  g.y = yv.y * (zv.y / (1.f + __expf(-zv.y)));
  g.z = yv.z * (zv.z / (1.f + __expf(-zv.z)));
  g.w = yv.w * (zv.w / (1.f + __expf(-zv.w)));
  float ssq = g.x * g.x + g.y * g.y + g.z * g.z + g.w * g.w;
  #pragma unroll
  for (int o = 16; o; o >>= 1) ssq += __shfl_xor_sync(0xFFFFFFFFu, ssq, o);
  __shared__ float red[8];
  if ((tid & 31) == 0) red[tid >> 5] = ssq;
  __syncthreads();
  float tot = red[0] + red[1] + red[2] + red[3] + red[4] + red[5] + red[6] + red[7];
  float scale = rsqrtf(tot * (1.f / DINNER) + EPSV);
  float4 w = *(const float4*)(nw + tid * 4);
  __half2* dst = (__half2*)(g_yh + (size_t)pos * DINNER + tid * 4);
  dst[0] = __floats2half2_rn(g.x * scale * w.x, g.y * scale * w.y);
  dst[1] = __floats2half2_rn(g.z * scale * w.z, g.w * scale * w.w);
}

// ---------------- launch ------------------------------------------------------
extern "C" void kernel_launch(void* const* d_in, const int* in_sizes, int n_in,
                              void* d_out, int out_size) {
  const float* x       = (const float*)d_in[0];
  const float* W_in    = (const float*)d_in[1];
  const float* conv_w  = (const float*)d_in[2];
  const float* conv_b  = (const float*)d_in[3];
  const float* dt_bias = (const float*)d_in[4];
  const float* A_log   = (const float*)d_in[5];
  const float* Dv      = (const float*)d_in[6];
  const float* nw      = (const float*)d_in[7];
  const float* W_out   = (const float*)d_in[8];
  float* out = (float*)d_out;

  void* p;
  cudaGetSymbolAddress(&p, g_zx);  float* zx = (float*)p;
  cudaGetSymbolAddress(&p, g_xh);  __half* xh  = (__half*)p;
  cudaGetSymbolAddress(&p, g_w1h); __half* w1h = (__half*)p;
  cudaGetSymbolAddress(&p, g_yh);  __half* yh  = (__half*)p;
  cudaGetSymbolAddress(&p, g_w2h); __half* w2h = (__half*)p;

  cudaFuncSetAttribute(chunk_kernel, cudaFuncAttributeMaxDynamicSharedMemorySize, CH_SMEM);
  cudaFuncSetAttribute(gemm_tc, cudaFuncAttributeMaxDynamicSharedMemorySize, SM_TOTAL);

  dim3 blk(256);
  // 0) fused prep
  prep_kernel<<<PREP_A + PREP_B + PREP_C, blk>>>(x, W_in, W_out);
  // 1) in-projection
  gemm_tc<<<dim3(NPAD1 / 128, NPOS / 128), dim3(128), SM_TOTAL>>>(xh, w1h, zx,
                                                                  DMODEL, DPROJ, DPROJ);
  // 2) fused conv+silu and dt+cumlog
  convdt_kernel<<<CONV_BLKS + 512, dim3(128)>>>(conv_w, conv_b, dt_bias, A_log);
  // 3) intra-chunk SSD
  chunk_kernel<<<BATCH * NH * NC, blk, CH_SMEM>>>(Dv);
  // 4) inter-chunk state scan
  scan_kernel<<<dim3(BATCH * NH, 8), dim3(128)>>>();
  // 5) inter-chunk correction
  inter_kernel<<<BATCH * NH * NC, blk>>>();
  // 6) gate + RMSNorm
  norm_kernel<<<NPOS, blk>>>(nw);
  // 7) out-projection
  gemm_tc<<<dim3(DMODEL / 128, NPOS / 128), dim3(128), SM_TOTAL>>>(yh, w2h, out,
                                                                   DINNER, DMODEL, DMODEL);
}

// round 17
// speedup vs baseline: 1.1452x; 1.0567x over previous
#include <cuda_runtime.h>
#include <cuda_fp16.h>
#include <cstdint>
#include <cstddef>

#define BATCH   2
#define SEQLEN  4096
#define DMODEL  512
#define DINNER  1024
#define NH      16
#define HD      64
#define DSTATE  64
#define CONVDIM 1152
#define DPROJ   2192
#define NPOS    (BATCH * SEQLEN)   // 8192
#define NC      64
#define CS      64
#define EPSV    1e-5f
#define NPAD1   2304

// ---------------- scratch (static device globals) ---------------------------
__device__ float  g_zx [(size_t)NPOS * DPROJ];
__device__ __half g_xbc[(size_t)NPOS * CONVDIM];
__device__ float  g_dt [NPOS * NH];
__device__ float  g_cl [BATCH * NH * SEQLEN];
__device__ __half g_S  [(size_t)BATCH * NH * NC * HD * DSTATE];   // chunk states
__device__ __half g_Sh [(size_t)BATCH * NH * NC * HD * DSTATE];   // prefix states
__device__ float  g_y  [(size_t)NPOS * DINNER];

__device__ __half g_xh [(size_t)NPOS * DMODEL];
__device__ __half g_w1h[(size_t)NPAD1 * DMODEL];
__device__ __half g_yh [(size_t)NPOS * DINNER];
__device__ __half g_w2h[(size_t)DMODEL * DINNER];

// ---------------- PTX helpers ------------------------------------------------
__device__ __forceinline__ uint32_t smem_u32(const void* p) {
  uint32_t a;
  asm("{ .reg .u64 t; cvta.to.shared.u64 t, %1; cvt.u32.u64 %0, t; }" : "=r"(a) : "l"(p));
  return a;
}
__device__ __forceinline__ void ldm4(uint32_t* r, uint32_t addr) {
  asm volatile("ldmatrix.sync.aligned.m8n8.x4.shared.b16 {%0,%1,%2,%3}, [%4];"
               : "=r"(r[0]), "=r"(r[1]), "=r"(r[2]), "=r"(r[3]) : "r"(addr));
}
__device__ __forceinline__ void ldm4t(uint32_t* r, uint32_t addr) {
  asm volatile("ldmatrix.sync.aligned.m8n8.x4.trans.shared.b16 {%0,%1,%2,%3}, [%4];"
               : "=r"(r[0]), "=r"(r[1]), "=r"(r[2]), "=r"(r[3]) : "r"(addr));
}
__device__ __forceinline__ void mma16816(float* c, const uint32_t* a, const uint32_t* b) {
  asm volatile(
      "mma.sync.aligned.m16n8k16.row.col.f32.f16.f16.f32 "
      "{%0,%1,%2,%3}, {%4,%5,%6,%7}, {%8,%9}, {%0,%1,%2,%3};"
      : "+f"(c[0]), "+f"(c[1]), "+f"(c[2]), "+f"(c[3])
      : "r"(a[0]), "r"(a[1]), "r"(a[2]), "r"(a[3]), "r"(b[0]), "r"(b[1]));
}
#define CPASYNC(dst, src) \
  asm volatile("cp.async.cg.shared.global [%0], [%1], 16;" :: "r"(dst), "l"(src))
#define CPCOMMIT() asm volatile("cp.async.commit_group;" ::: "memory")
#define CPWAIT(n)  asm volatile("cp.async.wait_group %0;" :: "n"(n) : "memory")
#define SWZ(off)   ((off) ^ (((off) >> 3) & 0x70))

// ---------------- HMMA GEMM (fp16): C = A @ B^T ------------------------------
#define SM_BUF   32768
#define SM_TOTAL (3 * SM_BUF)

__global__ __launch_bounds__(128, 2) void gemm_tc(
    const __half* __restrict__ A, const __half* __restrict__ B,
    float* __restrict__ C, int K, int N, int ldc) {
  extern __shared__ char smem[];
  const uint32_t sb = smem_u32(smem);
  const int tid = threadIdx.x, wid = tid >> 5, lane = tid & 31;
  const int bm = blockIdx.y * 128, bn = blockIdx.x * 128;
  const int wrow = wid & 1, wcol = wid >> 1;

  float acc[4][8][4];
  #pragma unroll
  for (int i = 0; i < 4; i++)
    #pragma unroll
    for (int j = 0; j < 8; j++)
      #pragma unroll
      for (int v = 0; v < 4; v++) acc[i][j][v] = 0.f;

  const int nK = K >> 6;

  #pragma unroll
  for (int pre = 0; pre < 2; pre++) {
    if (pre < nK) {
      const int k0 = pre << 6;
      const uint32_t bbuf = sb + pre * SM_BUF;
      #pragma unroll
      for (int it = 0; it < 16; it++) {
        const int u = it * 128 + tid;
        const int tile = u >> 10, idx = u & 1023;
        const int row = idx >> 3, c16 = idx & 7;
        const uint32_t dst = bbuf + tile * 16384 + SWZ((uint32_t)(row * 128 + c16 * 16));
        const __half* src = (tile == 0) ? A + (size_t)(bm + row) * K + k0 + c16 * 8
                                        : B + (size_t)(bn + row) * K + k0 + c16 * 8;
        CPASYNC(dst, src);
      }
    }
    CPCOMMIT();
  }

  int buf = 0;
  for (int i = 0; i < nK; i++) {
    if (i + 2 < nK) {
      const int k0 = (i + 2) << 6;
      const uint32_t bbuf = sb + ((buf + 2 >= 3) ? buf - 1 : buf + 2) * SM_BUF;
      #pragma unroll
      for (int it = 0; it < 16; it++) {
        const int u = it * 128 + tid;
        const int tile = u >> 10, idx = u & 1023;
        const int row = idx >> 3, c16 = idx & 7;
        const uint32_t dst = bbuf + tile * 16384 + SWZ((uint32_t)(row * 128 + c16 * 16));
        const __half* src = (tile == 0) ? A + (size_t)(bm + row) * K + k0 + c16 * 8
                                        : B + (size_t)(bn + row) * K + k0 + c16 * 8;
        CPASYNC(dst, src);
      }
    }
    CPCOMMIT();
    CPWAIT(2);
    __syncthreads();

    const uint32_t tb = sb + buf * SM_BUF;
    const int arow = wrow * 64 + (lane & 15);
    const int brow = wcol * 64 + (lane & 7) + ((lane >> 4) & 1) * 8;
    const int akb  = (lane >> 4) * 16;
    const int bkb  = ((lane >> 3) & 1) * 16;

    #pragma unroll
    for (int ks = 0; ks < 4; ks++) {
      uint32_t ah[4][4];
      #pragma unroll
      for (int mt = 0; mt < 4; mt++) {
        const uint32_t off = SWZ((uint32_t)((arow + mt * 16) * 128 + ks * 32 + akb));
        ldm4(ah[mt], tb + off);
      }
      #pragma unroll
      for (int p = 0; p < 4; p++) {
        uint32_t bf[4];
        const uint32_t off = SWZ((uint32_t)((brow + p * 16) * 128 + ks * 32 + bkb));
        ldm4(bf, tb + 16384 + off);
        #pragma unroll
        for (int mt = 0; mt < 4; mt++) {
          mma16816(acc[mt][2 * p],     ah[mt], &bf[0]);
          mma16816(acc[mt][2 * p + 1], ah[mt], &bf[2]);
        }
      }
    }
    __syncthreads();
    buf = (buf + 1 >= 3) ? 0 : buf + 1;
  }

  const int r0 = bm + wrow * 64 + (lane >> 2);
  const int c0 = bn + wcol * 64 + (lane & 3) * 2;
  #pragma unroll
  for (int mt = 0; mt < 4; mt++)
    #pragma unroll
    for (int nt = 0; nt < 8; nt++) {
      const int col = c0 + nt * 8;
      if (col < N) {
        const int row = r0 + mt * 16;
        *(float2*)&C[(size_t)row * ldc + col] =
            make_float2(acc[mt][nt][0], acc[mt][nt][1]);
        *(float2*)&C[(size_t)(row + 8) * ldc + col] =
            make_float2(acc[mt][nt][2], acc[mt][nt][3]);
      }
    }
}

// ---------------- fused prep: x->fp16 cast + both W transposes ---------------
#define PREP_A 16384
#define PREP_B 1152
#define PREP_C 512

__global__ __launch_bounds__(256) void prep_kernel(
    const float* __restrict__ x, const float* __restrict__ W_in,
    const float* __restrict__ W_out) {
  __shared__ float t[32][33];
  const int bid = blockIdx.x, tid = threadIdx.x;
  if (bid < PREP_A) {
    const int i = bid * 256 + tid;
    g_xh[i] = __float2half(x[i]);
    return;
  }
  const float* W;
  __half* th;
  int K, N, bx, by;
  if (bid < PREP_A + PREP_B) {
    const int lb = bid - PREP_A;
    W = W_in; th = g_w1h; K = DMODEL; N = DPROJ;
    bx = lb % (NPAD1 / 32); by = lb / (NPAD1 / 32);
  } else {
    const int lb = bid - PREP_A - PREP_B;
    W = W_out; th = g_w2h; K = DINNER; N = DMODEL;
    bx = lb % (DMODEL / 32); by = lb / (DMODEL / 32);
  }
  const int n0 = bx * 32, k0 = by * 32;
  const int tx = tid & 31, ty = tid >> 5;
  #pragma unroll
  for (int r = 0; r < 4; r++) {
    int k = k0 + ty + r * 8, n = n0 + tx;
    t[ty + r * 8][tx] = (n < N) ? W[(size_t)k * N + n] : 0.f;
  }
  __syncthreads();
  #pragma unroll
  for (int r = 0; r < 4; r++) {
    int n = n0 + ty + r * 8, k = k0 + tx;
    th[(size_t)n * K + k] = __float2half(t[tx][ty + r * 8]);
  }
}

// ---------------- fused conv+silu and dt+cumlog ------------------------------
#define CONV_BLKS 9216

__global__ __launch_bounds__(128) void convdt_kernel(
    const float* __restrict__ cw, const float* __restrict__ cb,
    const float* __restrict__ dtb, const float* __restrict__ alog) {
  const int bid = blockIdx.x, tid = threadIdx.x;
  if (bid < CONV_BLKS) {
    const int ch  = (bid % 9) * 128 + tid;
    const int grp = bid / 9;
    const size_t pos0 = (size_t)grp * 8;
    const int l0 = (int)(pos0 & (SEQLEN - 1));
    const float* src = g_zx + pos0 * DPROJ + DINNER + ch;
    const float w0 = cw[ch * 4 + 0], w1 = cw[ch * 4 + 1];
    const float w2 = cw[ch * 4 + 2], w3 = cw[ch * 4 + 3];
    const float bias = cb[ch];
    float v[11];
    #pragma unroll
    for (int j = 0; j < 3; j++)
      v[j] = (l0 >= 3 - j) ? src[(ptrdiff_t)(j - 3) * DPROJ] : 0.f;
    #pragma unroll
    for (int j = 0; j < 8; j++)
      v[3 + j] = src[(ptrdiff_t)j * DPROJ];
    __half* dst = g_xbc + pos0 * CONVDIM + ch;
    #pragma unroll
    for (int j = 0; j < 8; j++) {
      float a = bias + w0 * v[j] + w1 * v[j + 1] + w2 * v[j + 2] + w3 * v[j + 3];
      dst[(size_t)j * CONVDIM] = __float2half(a / (1.f + __expf(-a)));
    }
    return;
  }
  const int gw = ((bid - CONV_BLKS) * 128 + tid) >> 5;
  const int lane = tid & 31;
  const int c = gw & (NC - 1);
  const int bh = gw >> 6;
  const int b = bh >> 4, h = bh & (NH - 1);
  const int t0 = c * CS;
  const int pos0 = b * SEQLEN + t0 + lane;
  const float bsh = dtb[h];
  const float A = -expf(alog[h]);
  float v0 = g_zx[(size_t)pos0 * DPROJ + DINNER + CONVDIM + h] + bsh;
  float v1 = g_zx[(size_t)(pos0 + 32) * DPROJ + DINNER + CONVDIM + h] + bsh;
  float sp0 = (v0 > 20.f) ? v0 : log1pf(expf(v0));
  float sp1 = (v1 > 20.f) ? v1 : log1pf(expf(v1));
  g_dt[pos0 * NH + h] = sp0;
  g_dt[(pos0 + 32) * NH + h] = sp1;
  float x0 = A * sp0, x1 = A * sp1;
  #pragma unroll
  for (int o = 1; o < 32; o <<= 1) {
    float t = __shfl_up_sync(0xFFFFFFFFu, x0, o);
    if (lane >= o) x0 += t;
  }
  float tot0 = __shfl_sync(0xFFFFFFFFu, x0, 31);
  #pragma unroll
  for (int o = 1; o < 32; o <<= 1) {
    float t = __shfl_up_sync(0xFFFFFFFFu, x1, o);
    if (lane >= o) x1 += t;
  }
  x1 += tot0;
  g_cl[bh * SEQLEN + t0 + lane] = x0;
  g_cl[bh * SEQLEN + t0 + 32 + lane] = x1;
}

#define CLDH 72
#define CLDB 144

// ---------------- state kernel: S = (w .* X)^T @ B (fp16 out) ----------------
__global__ __launch_bounds__(256) void state_kernel() {
  __shared__ __align__(16) __half sB [4608];   // [64][72] B[s][n]
  __shared__ __align__(16) __half sXW[4608];   // [64][72] XW[s][p]
  __shared__ float scl[64];
  __shared__ float sdt[64];

  const int bid = blockIdx.x;
  const int c = bid & (NC - 1);
  const int bh = bid >> 6;
  const int h = bh & (NH - 1);
  const int b = bh >> 4;
  const int tid = threadIdx.x;
  const int t0 = c * CS;
  const int wid = tid >> 5, lane = tid & 31;

  {
    const int row = tid >> 2, cs = (tid & 3) * 16;
    const __half* base = g_xbc + (size_t)(b * SEQLEN + t0 + row) * CONVDIM;
    #pragma unroll
    for (int q = 0; q < 2; q++) {
      const int col = cs + q * 8;
      *(uint4*)(sB  + row * CLDH + col) = *(const uint4*)(base + DINNER + col);
      *(uint4*)(sXW + row * CLDH + col) = *(const uint4*)(base + h * HD + col);
    }
    if (tid < 64) {
      scl[tid] = g_cl[bh * SEQLEN + t0 + tid];
      sdt[tid] = g_dt[(b * SEQLEN + t0 + tid) * NH + h];
    }
  }
  __syncthreads();
  // scale XW rows in place: XW[s][p] = w[s]*X[s][p]
  {
    const float Ltot = scl[63];
    const int row = tid >> 2, cs = (tid & 3) * 16;
    const float w = __expf(Ltot - scl[row]) * sdt[row];
    #pragma unroll
    for (int q = 0; q < 2; q++) {
      uint4 v = *(uint4*)(sXW + row * CLDH + cs + q * 8);
      __half* hv = (__half*)&v;
      #pragma unroll
      for (int j = 0; j < 8; j++)
        hv[j] = __float2half(__half2float(hv[j]) * w);
      *(uint4*)(sXW + row * CLDH + cs + q * 8) = v;
    }
  }
  __syncthreads();

  const uint32_t uB = smem_u32(sB), uXW = smem_u32(sXW);
  const int mt0 = (wid & 3) * 16;
  const int nt0 = (wid >> 2) * 32;
  const int bofft_row = (lane & 7) + ((lane >> 3) & 1) * 8;
  const int bofft_b   = ((lane >> 4) & 1) * 16;
  const int aofft_row = (lane & 7) + ((lane >> 4) & 1) * 8;
  const int aofft_b   = ((lane >> 3) & 1) * 16;
  const int rb = mt0 + (lane >> 2);
  const int cb = nt0 + (lane & 3) * 2;

  float acc[4][4];
  #pragma unroll
  for (int nt = 0; nt < 4; nt++)
    #pragma unroll
    for (int v = 0; v < 4; v++) acc[nt][v] = 0.f;
  #pragma unroll
  for (int ks = 0; ks < 4; ks++) {
    uint32_t af[4];
    ldm4t(af, uXW + (uint32_t)((ks * 16 + aofft_row) * CLDB + mt0 * 2 + aofft_b));
    #pragma unroll
    for (int p = 0; p < 2; p++) {
      uint32_t bf[4];
      ldm4t(bf, uB + (uint32_t)((ks * 16 + bofft_row) * CLDB
                                + (nt0 + p * 16) * 2 + bofft_b));
      mma16816(acc[2 * p],     af, &bf[0]);
      mma16816(acc[2 * p + 1], af, &bf[2]);
    }
  }
  #pragma unroll
  for (int nt = 0; nt < 4; nt++) {
    const int n = cb + nt * 8;
    *(__half2*)&g_S[(size_t)bid * 4096 + rb * 64 + n] =
        __floats2half2_rn(acc[nt][0], acc[nt][1]);
    *(__half2*)&g_S[(size_t)bid * 4096 + (rb + 8) * 64 + n] =
        __floats2half2_rn(acc[nt][2], acc[nt][3]);
  }
}

// ---------------- inter-chunk state scan (fp16 in, fp16 prefix out) ---------
__global__ __launch_bounds__(128) void scan_kernel() {
  const int bh = blockIdx.x;
  const int slice = blockIdx.y;
  const int tid = threadIdx.x;
  const int off = slice * 512 + tid * 4;
  float run[4] = {0.f, 0.f, 0.f, 0.f};
  for (int c = 0; c < NC; c++) {
    float a = __expf(g_cl[bh * SEQLEN + c * CS + CS - 1]);
    const __half2* p = (const __half2*)(g_S + (size_t)(bh * NC + c) * 4096 + off);
    float2 v01 = __half22float2(p[0]);
    float2 v23 = __half22float2(p[1]);
    __half2* d = (__half2*)(g_Sh + (size_t)(bh * NC + c) * 4096 + off);
    d[0] = __floats2half2_rn(run[0], run[1]);
    d[1] = __floats2half2_rn(run[2], run[3]);
    run[0] = a * run[0] + v01.x;
    run[1] = a * run[1] + v01.y;
    run[2] = a * run[2] + v23.x;
    run[3] = a * run[3] + v23.y;
  }
}

// ---------------- main SSD kernel: intra + inter fused, single y write ------
#define CH_SMEM (5 * 9216 + 128 * 4)

__global__ __launch_bounds__(256) void main_kernel(const float* __restrict__ Dv) {
  extern __shared__ __align__(16) __half sh[];
  __half* sC  = sh;            // [64][72] C[t][n]
  __half* sB  = sh + 4608;     // [64][72] B[s][n]
  __half* sX  = sh + 9216;     // [64][72] X[s][p]
  __half* sM  = sh + 13824;    // [64][72] M[t][s]
  __half* sSp = sh + 18432;    // [64][72] Sprev[p][n]
  float* scl = (float*)(sh + 23040);
  float* sdt = scl + 64;

  const int bid = blockIdx.x;
  const int c = bid & (NC - 1);
  const int bh = bid >> 6;
  const int h = bh & (NH - 1);
  const int b = bh >> 4;
  const int tid = threadIdx.x;
  const int t0 = c * CS;
  const int wid = tid >> 5, lane = tid & 31;

  {
    const int row = tid >> 2, cs = (tid & 3) * 16;
    const __half* base = g_xbc + (size_t)(b * SEQLEN + t0 + row) * CONVDIM;
    #pragma unroll
    for (int q = 0; q < 2; q++) {
      const int col = cs + q * 8;
      *(uint4*)(sB + row * CLDH + col) = *(const uint4*)(base + DINNER + col);
      *(uint4*)(sC + row * CLDH + col) = *(const uint4*)(base + DINNER + DSTATE + col);
      *(uint4*)(sX + row * CLDH + col) = *(const uint4*)(base + h * HD + col);
      *(uint4*)(sSp + row * CLDH + col) =
          *(const uint4*)(g_Sh + (size_t)bid * 4096 + row * 64 + col);
    }
    if (tid < 64) {
      scl[tid] = g_cl[bh * SEQLEN + t0 + tid];
      sdt[tid] = g_dt[(b * SEQLEN + t0 + tid) * NH + h];
    }
  }
  __syncthreads();

  const uint32_t uC = smem_u32(sC), uB = smem_u32(sB), uX = smem_u32(sX);
  const uint32_t uM = smem_u32(sM), uSp = smem_u32(sSp);
  const int mt0 = (wid & 3) * 16;
  const int nt0 = (wid >> 2) * 32;
  const int aoff = (lane & 15) * CLDB + (lane >> 4) * 16;
  const int boff = ((lane & 7) + ((lane >> 4) & 1) * 8) * CLDB + ((lane >> 3) & 1) * 16;
  const int bofft_row = (lane & 7) + ((lane >> 3) & 1) * 8;
  const int bofft_b   = ((lane >> 4) & 1) * 16;
  const int rb = mt0 + (lane >> 2);
  const int cb = nt0 + (lane & 3) * 2;

  // ---- phase 1: shared A-fragment (C rows t) feeds TWO GEMMs ----
  //   m0   += C @ B^T      (decay matrix precursor)
  //   acc2 += C @ Sprev^T  (inter-chunk contribution, scaled at epilogue)
  float m0[4][4], acc2[4][4];
  #pragma unroll
  for (int nt = 0; nt < 4; nt++)
    #pragma unroll
    for (int v = 0; v < 4; v++) { m0[nt][v] = 0.f; acc2[nt][v] = 0.f; }
  #pragma unroll
  for (int ks = 0; ks < 4; ks++) {
    uint32_t af[4];
    ldm4(af, uC + (uint32_t)(mt0 * CLDB + aoff + ks * 32));
    #pragma unroll
    for (int p = 0; p < 2; p++) {
      uint32_t bf[4], sf[4];
      ldm4(bf, uB  + (uint32_t)((nt0 + p * 16) * CLDB + boff + ks * 32));
      ldm4(sf, uSp + (uint32_t)((nt0 + p * 16) * CLDB + boff + ks * 32));
      mma16816(m0[2 * p],       af, &bf[0]);
      mma16816(m0[2 * p + 1],   af, &bf[2]);
      mma16816(acc2[2 * p],     af, &sf[0]);
      mma16816(acc2[2 * p + 1], af, &sf[2]);
    }
  }
  // masked decay -> sM (half2 stores)
  {
    const float et1 = scl[rb], et2 = scl[rb + 8];
    #pragma unroll
    for (int nt = 0; nt < 4; nt++) {
      const int s0 = cb + nt * 8;
      const float d0 = sdt[s0], d1 = sdt[s0 + 1];
      const float l0 = scl[s0], l1 = scl[s0 + 1];
      float v0 = (s0     <= rb) ? m0[nt][0] * __expf(et1 - l0) * d0 : 0.f;
      float v1 = (s0 + 1 <= rb) ? m0[nt][1] * __expf(et1 - l1) * d1 : 0.f;
      *(__half2*)(sM + rb * CLDH + s0) = __floats2half2_rn(v0, v1);
      float v2 = (s0     <= rb + 8) ? m0[nt][2] * __expf(et2 - l0) * d0 : 0.f;
      float v3 = (s0 + 1 <= rb + 8) ? m0[nt][3] * __expf(et2 - l1) * d1 : 0.f;
      *(__half2*)(sM + (rb + 8) * CLDH + s0) = __floats2half2_rn(v2, v3);
    }
  }
  __syncthreads();

  // ---- phase 2: acc = M @ X (B trans from X[s][p]) ----
  float acc[4][4];
  #pragma unroll
  for (int nt = 0; nt < 4; nt++)
    #pragma unroll
    for (int v = 0; v < 4; v++) acc[nt][v] = 0.f;
  #pragma unroll
  for (int ks = 0; ks < 4; ks++) {
    uint32_t af[4];
    ldm4(af, uM + (uint32_t)(mt0 * CLDB + aoff + ks * 32));
    #pragma unroll
    for (int p = 0; p < 2; p++) {
      uint32_t bf[4];
      ldm4t(bf, uX + (uint32_t)((ks * 16 + bofft_row) * CLDB
                                + (nt0 + p * 16) * 2 + bofft_b));
      mma16816(acc[2 * p],     af, &bf[0]);
      mma16816(acc[2 * p + 1], af, &bf[2]);
    }
  }

  // ---- epilogue: y = acc + e_t * acc2 + D * x  (single fp32 write) ----
  {
    const float Dh = Dv[h];
    const float e1 = __expf(scl[rb]);
    const float e2 = __expf(scl[rb + 8]);
    #pragma unroll
    for (int nt = 0; nt < 4; nt++) {
      const int p = cb + nt * 8;
      const int t1 = rb, t2 = rb + 8;
      float2 x1 = __half22float2(*(__half2*)(sX + t1 * CLDH + p));
      float2 x2 = __half22float2(*(__half2*)(sX + t2 * CLDH + p));
      float2 o01 = make_float2(acc[nt][0] + e1 * acc2[nt][0] + Dh * x1.x,
                               acc[nt][1] + e1 * acc2[nt][1] + Dh * x1.y);
      float2 o23 = make_float2(acc[nt][2] + e2 * acc2[nt][2] + Dh * x2.x,
                               acc[nt][3] + e2 * acc2[nt][3] + Dh * x2.y);
      *(float2*)&g_y[(size_t)(b * SEQLEN + t0 + t1) * DINNER + h * HD + p] = o01;
      *(float2*)&g_y[(size_t)(b * SEQLEN + t0 + t2) * DINNER + h * HD + p] = o23;
    }
  }
}

// ---------------- gate + RMSNorm, emits fp16 ---------------------------------
__global__ __launch_bounds__(256) void norm_kernel(const float* __restrict__ nw) {
  const int pos = blockIdx.x, tid = threadIdx.x;
  float4 yv = *(const float4*)(g_y  + (size_t)pos * DINNER + tid * 4);
  float4 zv = *(const float4*)(g_zx + (size_t)pos * DPROJ  + tid * 4);
  float4 g;
  g.x = yv.x * (zv.x / (1.f + __expf(-zv.x)));
  g.y = yv.y * (zv.y / (1.f + __expf(-zv.y)));
  g.z = yv.z * (zv.z / (1.f + __expf(-zv.z)));
  g.w = yv.w * (zv.w / (1.f + __expf(-zv.w)));
  float ssq = g.x * g.x + g.y * g.y + g.z * g.z + g.w * g.w;
  #pragma unroll
  for (int o = 16; o; o >>= 1) ssq += __shfl_xor_sync(0xFFFFFFFFu, ssq, o);
  __shared__ float red[8];
  if ((tid & 31) == 0) red[tid >> 5] = ssq;
  __syncthreads();
  float tot = red[0] + red[1] + red[2] + red[3] + red[4] + red[5] + red[6] + red[7];
  float scale = rsqrtf(tot * (1.f / DINNER) + EPSV);
  float4 w = *(const float4*)(nw + tid * 4);
  __half2* dst = (__half2*)(g_yh + (size_t)pos * DINNER + tid * 4);
  dst[0] = __floats2half2_rn(g.x * scale * w.x, g.y * scale * w.y);
  dst[1] = __floats2half2_rn(g.z * scale * w.z, g.w * scale * w.w);
}

// ---------------- launch ------------------------------------------------------
extern "C" void kernel_launch(void* const* d_in, const int* in_sizes, int n_in,
                              void* d_out, int out_size) {
  const float* x       = (const float*)d_in[0];
  const float* W_in    = (const float*)d_in[1];
  const float* conv_w  = (const float*)d_in[2];
  const float* conv_b  = (const float*)d_in[3];
  const float* dt_bias = (const float*)d_in[4];
  const float* A_log   = (const float*)d_in[5];
  const float* Dv      = (const float*)d_in[6];
  const float* nw      = (const float*)d_in[7];
  const float* W_out   = (const float*)d_in[8];
  float* out = (float*)d_out;

  void* p;
  cudaGetSymbolAddress(&p, g_zx);  float* zx = (float*)p;
  cudaGetSymbolAddress(&p, g_xh);  __half* xh  = (__half*)p;
  cudaGetSymbolAddress(&p, g_w1h); __half* w1h = (__half*)p;
  cudaGetSymbolAddress(&p, g_yh);  __half* yh  = (__half*)p;
  cudaGetSymbolAddress(&p, g_w2h); __half* w2h = (__half*)p;

  cudaFuncSetAttribute(main_kernel, cudaFuncAttributeMaxDynamicSharedMemorySize, CH_SMEM);
  cudaFuncSetAttribute(gemm_tc, cudaFuncAttributeMaxDynamicSharedMemorySize, SM_TOTAL);

  dim3 blk(256);
  // 0) fused prep
  prep_kernel<<<PREP_A + PREP_B + PREP_C, blk>>>(x, W_in, W_out);
  // 1) in-projection
  gemm_tc<<<dim3(NPAD1 / 128, NPOS / 128), dim3(128), SM_TOTAL>>>(xh, w1h, zx,
                                                                  DMODEL, DPROJ, DPROJ);
  // 2) fused conv+silu and dt+cumlog
  convdt_kernel<<<CONV_BLKS + 512, dim3(128)>>>(conv_w, conv_b, dt_bias, A_log);
  // 3) chunk states (GEMM3 only)
  state_kernel<<<BATCH * NH * NC, blk>>>();
  // 4) inter-chunk state scan
  scan_kernel<<<dim3(BATCH * NH, 8), dim3(128)>>>();
  // 5) main SSD: intra + inter fused, single y write
  main_kernel<<<BATCH * NH * NC, blk, CH_SMEM>>>(Dv);
  // 6) gate + RMSNorm
  norm_kernel<<<NPOS, blk>>>(nw);
  // 7) out-projection
  gemm_tc<<<dim3(DMODEL / 128, NPOS / 128), dim3(128), SM_TOTAL>>>(yh, w2h, out,
                                                                   DINNER, DMODEL, DMODEL);
}